// round 2
// baseline (speedup 1.0000x reference)
#include <cuda_runtime.h>
#include <cstdint>
#include <cstddef>

#define NROW 512
#define DDIM 128
#define NPAIR (NROW * NROW)          /* 262144 rows */
#define WCOLS 640                    /* 256 p_in + 256 g_in + 128 g_out */

/* -------- scratch (static device globals; no allocations allowed) -------- */
static __device__ float g_left [(size_t)DDIM * NPAIR];   /* [d][i*512+k] */
static __device__ float g_right[(size_t)DDIM * NPAIR];   /* [d][j*512+k] */
static __device__ float g_gate [(size_t)NPAIR * DDIM];   /* [row][e]     */
static __device__ float g_outT [(size_t)DDIM * NPAIR];   /* [d][i*512+j] */
static __device__ float g_wT   [DDIM * WCOLS];           /* [d][h]       */
static __device__ float g_wOT  [DDIM * DDIM];            /* [h][d] = p_out_w[d][h] */

/* ------------------------- weight transposes ----------------------------- */
__global__ void kprep(const float* __restrict__ p_in_w, const float* __restrict__ g_in_w,
                      const float* __restrict__ g_out_w, const float* __restrict__ p_out_w)
{
    int idx = blockIdx.x * blockDim.x + threadIdx.x;
    if (idx < DDIM * WCOLS) {
        int d = idx / WCOLS, h = idx % WCOLS;
        float v;
        if (h < 256)       v = p_in_w[h * DDIM + d];
        else if (h < 512)  v = g_in_w[(h - 256) * DDIM + d];
        else               v = g_out_w[(h - 512) * DDIM + d];
        g_wT[idx] = v;
    } else if (idx < DDIM * WCOLS + DDIM * DDIM) {
        int k = idx - DDIM * WCOLS;
        int h = k >> 7, d = k & 127;
        g_wOT[k] = p_out_w[d * DDIM + h];
    }
}

/* --------- stage 1: LN + fused projections (p_in, g_in, g_out gate) ------ */
/* 640 threads: thread t owns output column t for 32 rows.                    */
__global__ void __launch_bounds__(640) kproj(const float* __restrict__ pair,
                                             const float* __restrict__ lnw,
                                             const float* __restrict__ lnb)
{
    __shared__ float rows[32 * 128];    /* later reused as stageL (swizzled) */
    __shared__ float pstage[32 * 256];  /* first 4096 reused as stageR       */

    const int tid = threadIdx.x;
    const int rowbase = blockIdx.x * 32;

    /* load 32 rows */
    const float* src = pair + (size_t)rowbase * DDIM;
    for (int idx = tid; idx < 32 * 128; idx += 640) rows[idx] = src[idx];
    __syncthreads();

    /* LayerNorm: one warp per row (20 warps, 32 rows) */
    const int wid = tid >> 5, lane = tid & 31;
    {
        float w0 = lnw[lane], w1 = lnw[lane + 32], w2 = lnw[lane + 64], w3 = lnw[lane + 96];
        float b0 = lnb[lane], b1 = lnb[lane + 32], b2 = lnb[lane + 64], b3 = lnb[lane + 96];
        for (int r = wid; r < 32; r += 20) {
            float* rp = rows + r * 128;
            float v0 = rp[lane], v1 = rp[lane + 32], v2 = rp[lane + 64], v3 = rp[lane + 96];
            float s = v0 + v1 + v2 + v3;
            #pragma unroll
            for (int o = 16; o > 0; o >>= 1) s += __shfl_xor_sync(0xffffffffu, s, o);
            float mu = s * (1.0f / 128.0f);
            float d0 = v0 - mu, d1 = v1 - mu, d2 = v2 - mu, d3 = v3 - mu;
            float q = d0 * d0 + d1 * d1 + d2 * d2 + d3 * d3;
            #pragma unroll
            for (int o = 16; o > 0; o >>= 1) q += __shfl_xor_sync(0xffffffffu, q, o);
            float rstd = rsqrtf(q * (1.0f / 128.0f) + 1e-5f);
            rp[lane]      = d0 * rstd * w0 + b0;
            rp[lane + 32] = d1 * rstd * w1 + b1;
            rp[lane + 64] = d2 * rstd * w2 + b2;
            rp[lane + 96] = d3 * rstd * w3 + b3;
        }
    }
    __syncthreads();

    /* projection: acc[r] = dot(rows[r], wT[:,tid]) */
    float acc[32];
    #pragma unroll
    for (int r = 0; r < 32; r++) acc[r] = 0.0f;
    const float* wp = g_wT + tid;
    for (int d4 = 0; d4 < 128; d4 += 4) {
        float wa = wp[(d4 + 0) * WCOLS];
        float wb = wp[(d4 + 1) * WCOLS];
        float wc = wp[(d4 + 2) * WCOLS];
        float wd = wp[(d4 + 3) * WCOLS];
        #pragma unroll
        for (int r = 0; r < 32; r++) {
            float4 x = *(const float4*)(rows + r * 128 + d4);
            acc[r] += wa * x.x + wb * x.y + wc * x.z + wd * x.w;
        }
    }

    /* gate (cols 512..639): sigmoid -> global, row-major [row][e] */
    if (tid >= 512) {
        int e = tid - 512;
        #pragma unroll
        for (int r = 0; r < 32; r++) {
            float s = 1.0f / (1.0f + __expf(-acc[r]));
            g_gate[(size_t)(rowbase + r) * DDIM + e] = s;
        }
    }

    /* p cols stage */
    if (tid < 256) {
        #pragma unroll
        for (int r = 0; r < 32; r++) pstage[r * 256 + tid] = acc[r];
    }
    __syncthreads();

    /* g cols: sigmoid(g)*p into registers */
    if (tid >= 256 && tid < 512) {
        int h = tid - 256;
        #pragma unroll
        for (int r = 0; r < 32; r++) {
            float s = 1.0f / (1.0f + __expf(-acc[r]));
            acc[r] = s * pstage[r * 256 + h];
        }
    }
    __syncthreads();   /* all pstage/rows reads done; safe to overwrite */

    /* stage left/right with XOR swizzle for conflict-free transpose */
    if (tid >= 256 && tid < 512) {
        int h = tid - 256;
        float* stg = (h < 128) ? rows : pstage;
        int hh = h & 127;
        #pragma unroll
        for (int r = 0; r < 32; r++) stg[r * 128 + ((hh + r) & 127)] = acc[r];
    }
    __syncthreads();

    /* coalesced writeout to channel-major layout [d][row] */
    for (int idx = tid; idx < 4096; idx += 640) {
        int h = idx >> 5, r = idx & 31;
        float lv = rows  [r * 128 + ((h + r) & 127)];
        float rv = pstage[r * 128 + ((h + r) & 127)];
        g_left [(size_t)h * NPAIR + rowbase + r] = lv;
        g_right[(size_t)h * NPAIR + rowbase + r] = rv;
    }
}

/* --------- stage 2: 128 batched SGEMM-NT 512x512x512 (the einsum) -------- */
__global__ void __launch_bounds__(256) kgemm()
{
    __shared__ float As[32 * 65];   /* [k][i], padded */
    __shared__ float Bs[32 * 65];   /* [k][j], padded */

    const int d = blockIdx.z;
    const float* A = g_left  + (size_t)d * NPAIR + (size_t)blockIdx.y * 64 * 512;
    const float* B = g_right + (size_t)d * NPAIR + (size_t)blockIdx.x * 64 * 512;

    const int tid = threadIdx.x;
    const int r0 = tid >> 3, k4 = (tid & 7) * 4;
    const int tx = tid & 15, ty = tid >> 4;

    float c[4][4];
    #pragma unroll
    for (int i = 0; i < 4; i++)
        #pragma unroll
        for (int j = 0; j < 4; j++) c[i][j] = 0.0f;

    for (int kt = 0; kt < 512; kt += 32) {
        float4 a0 = *(const float4*)(A + (size_t)r0 * 512 + kt + k4);
        float4 a1 = *(const float4*)(A + (size_t)(r0 + 32) * 512 + kt + k4);
        float4 b0 = *(const float4*)(B + (size_t)r0 * 512 + kt + k4);
        float4 b1 = *(const float4*)(B + (size_t)(r0 + 32) * 512 + kt + k4);
        __syncthreads();
        As[(k4 + 0) * 65 + r0] = a0.x; As[(k4 + 1) * 65 + r0] = a0.y;
        As[(k4 + 2) * 65 + r0] = a0.z; As[(k4 + 3) * 65 + r0] = a0.w;
        As[(k4 + 0) * 65 + r0 + 32] = a1.x; As[(k4 + 1) * 65 + r0 + 32] = a1.y;
        As[(k4 + 2) * 65 + r0 + 32] = a1.z; As[(k4 + 3) * 65 + r0 + 32] = a1.w;
        Bs[(k4 + 0) * 65 + r0] = b0.x; Bs[(k4 + 1) * 65 + r0] = b0.y;
        Bs[(k4 + 2) * 65 + r0] = b0.z; Bs[(k4 + 3) * 65 + r0] = b0.w;
        Bs[(k4 + 0) * 65 + r0 + 32] = b1.x; Bs[(k4 + 1) * 65 + r0 + 32] = b1.y;
        Bs[(k4 + 2) * 65 + r0 + 32] = b1.z; Bs[(k4 + 3) * 65 + r0 + 32] = b1.w;
        __syncthreads();
        #pragma unroll
        for (int kk = 0; kk < 32; kk++) {
            float a[4], b[4];
            #pragma unroll
            for (int q = 0; q < 4; q++) a[q] = As[kk * 65 + ty * 4 + q];
            #pragma unroll
            for (int q = 0; q < 4; q++) b[q] = Bs[kk * 65 + tx * 4 + q];
            #pragma unroll
            for (int i = 0; i < 4; i++)
                #pragma unroll
                for (int j = 0; j < 4; j++) c[i][j] += a[i] * b[j];
        }
    }

    const float inv = 1.0f / 512.0f;
    float* C = g_outT + (size_t)d * NPAIR
             + (size_t)(blockIdx.y * 64 + ty * 4) * 512 + blockIdx.x * 64 + tx * 4;
    #pragma unroll
    for (int i = 0; i < 4; i++) {
        float4 v = make_float4(c[i][0] * inv, c[i][1] * inv, c[i][2] * inv, c[i][3] * inv);
        *(float4*)(C + (size_t)i * 512) = v;
    }
}

/* --------- stage 3: LN over d + p_out projection + gate ------------------ */
__global__ void __launch_bounds__(256) kout(const float* __restrict__ lnw,
                                            const float* __restrict__ lnb,
                                            float* __restrict__ outp)
{
    __shared__ float o[64 * 129];   /* [j][d], padded */

    const int i = blockIdx.y;
    const int j0 = blockIdx.x * 64;
    const int tid = threadIdx.x;

    for (int idx = tid; idx < 64 * 128; idx += 256) {
        int dd = idx >> 6, j = idx & 63;
        o[j * 129 + dd] = g_outT[(size_t)dd * NPAIR + (size_t)i * 512 + j0 + j];
    }
    __syncthreads();

    const int wid = tid >> 5, lane = tid & 31;
    {
        float w0 = lnw[lane], w1 = lnw[lane + 32], w2 = lnw[lane + 64], w3 = lnw[lane + 96];
        float b0 = lnb[lane], b1 = lnb[lane + 32], b2 = lnb[lane + 64], b3 = lnb[lane + 96];
        for (int j = wid; j < 64; j += 8) {
            float* rp = o + j * 129;
            float v0 = rp[lane], v1 = rp[lane + 32], v2 = rp[lane + 64], v3 = rp[lane + 96];
            float s = v0 + v1 + v2 + v3;
            #pragma unroll
            for (int off = 16; off > 0; off >>= 1) s += __shfl_xor_sync(0xffffffffu, s, off);
            float mu = s * (1.0f / 128.0f);
            float d0 = v0 - mu, d1 = v1 - mu, d2 = v2 - mu, d3 = v3 - mu;
            float q = d0 * d0 + d1 * d1 + d2 * d2 + d3 * d3;
            #pragma unroll
            for (int off = 16; off > 0; off >>= 1) q += __shfl_xor_sync(0xffffffffu, q, off);
            float rstd = rsqrtf(q * (1.0f / 128.0f) + 1e-5f);
            rp[lane]      = d0 * rstd * w0 + b0;
            rp[lane + 32] = d1 * rstd * w1 + b1;
            rp[lane + 64] = d2 * rstd * w2 + b2;
            rp[lane + 96] = d3 * rstd * w3 + b3;
        }
    }
    __syncthreads();

    const int d = tid & 127, half = tid >> 7;
    for (int jc = half * 32; jc < half * 32 + 32; jc += 16) {
        float acc[16];
        #pragma unroll
        for (int r = 0; r < 16; r++) acc[r] = 0.0f;
        for (int h = 0; h < 128; h++) {
            float w = g_wOT[h * 128 + d];
            #pragma unroll
            for (int r = 0; r < 16; r++) acc[r] += w * o[(jc + r) * 129 + h];
        }
        #pragma unroll
        for (int r = 0; r < 16; r++) {
            size_t row = (size_t)i * 512 + j0 + jc + r;
            outp[row * 128 + d] = g_gate[row * 128 + d] * acc[r];
        }
    }
}

/* ------------------------------- launch ---------------------------------- */
extern "C" void kernel_launch(void* const* d_in, const int* in_sizes, int n_in,
                              void* d_out, int out_size)
{
    const float* pair     = (const float*)d_in[0];
    const float* ln_in_w  = (const float*)d_in[1];
    const float* ln_in_b  = (const float*)d_in[2];
    const float* p_in_w   = (const float*)d_in[3];
    const float* g_in_w   = (const float*)d_in[4];
    const float* ln_out_w = (const float*)d_in[5];
    const float* ln_out_b = (const float*)d_in[6];
    const float* p_out_w  = (const float*)d_in[7];
    const float* g_out_w  = (const float*)d_in[8];
    float* out = (float*)d_out;

    kprep<<<(DDIM * WCOLS + DDIM * DDIM + 255) / 256, 256>>>(p_in_w, g_in_w, g_out_w, p_out_w);
    kproj<<<NPAIR / 32, 640>>>(pair, ln_in_w, ln_in_b);
    kgemm<<<dim3(8, 8, 128), 256>>>();
    kout<<<dim3(8, 512), 256>>>(ln_out_w, ln_out_b, out);
}

// round 6
// speedup vs baseline: 1.2997x; 1.2997x over previous
#include <cuda_runtime.h>
#include <cstdint>
#include <cstddef>

#define NROW 512
#define DDIM 128
#define NPAIR (NROW * NROW)          /* 262144 rows */
#define WCOLS 640                    /* 256 p_in + 256 g_in + 128 g_out */

/* -------- scratch (static device globals; no allocations allowed) -------- */
static __device__ float g_left [(size_t)DDIM * NPAIR];   /* [d][i*512+k] */
static __device__ float g_right[(size_t)DDIM * NPAIR];   /* [d][j*512+k] */
static __device__ float g_gate [(size_t)NPAIR * DDIM];   /* [row][e]     */
static __device__ float g_outT [(size_t)DDIM * NPAIR];   /* [d][i*512+j] */
static __device__ float g_wT   [DDIM * WCOLS];           /* [d][h]       */
static __device__ float g_wOT  [DDIM * DDIM];            /* [h][d] = p_out_w[d][h] */

/* ------------------------- weight transposes ----------------------------- */
__global__ void kprep(const float* __restrict__ p_in_w, const float* __restrict__ g_in_w,
                      const float* __restrict__ g_out_w, const float* __restrict__ p_out_w)
{
    int idx = blockIdx.x * blockDim.x + threadIdx.x;
    if (idx < DDIM * WCOLS) {
        int d = idx / WCOLS, h = idx % WCOLS;
        float v;
        if (h < 256)       v = p_in_w[h * DDIM + d];
        else if (h < 512)  v = g_in_w[(h - 256) * DDIM + d];
        else               v = g_out_w[(h - 512) * DDIM + d];
        g_wT[idx] = v;
    } else if (idx < DDIM * WCOLS + DDIM * DDIM) {
        int k = idx - DDIM * WCOLS;
        int h = k >> 7, d = k & 127;
        g_wOT[k] = p_out_w[d * DDIM + h];
    }
}

/* --------- stage 1: LN + fused projections (p_in, g_in, g_out gate) ------ */
__global__ void __launch_bounds__(640) kproj(const float* __restrict__ pair,
                                             const float* __restrict__ lnw,
                                             const float* __restrict__ lnb)
{
    __shared__ float rows[32 * 128];    /* later reused as stageL (swizzled) */
    __shared__ float pstage[32 * 256];  /* first 4096 reused as stageR       */

    const int tid = threadIdx.x;
    const int rowbase = blockIdx.x * 32;

    const float* src = pair + (size_t)rowbase * DDIM;
    for (int idx = tid; idx < 32 * 128; idx += 640) rows[idx] = src[idx];
    __syncthreads();

    const int wid = tid >> 5, lane = tid & 31;
    {
        float w0 = lnw[lane], w1 = lnw[lane + 32], w2 = lnw[lane + 64], w3 = lnw[lane + 96];
        float b0 = lnb[lane], b1 = lnb[lane + 32], b2 = lnb[lane + 64], b3 = lnb[lane + 96];
        for (int r = wid; r < 32; r += 20) {
            float* rp = rows + r * 128;
            float v0 = rp[lane], v1 = rp[lane + 32], v2 = rp[lane + 64], v3 = rp[lane + 96];
            float s = v0 + v1 + v2 + v3;
            #pragma unroll
            for (int o = 16; o > 0; o >>= 1) s += __shfl_xor_sync(0xffffffffu, s, o);
            float mu = s * (1.0f / 128.0f);
            float d0 = v0 - mu, d1 = v1 - mu, d2 = v2 - mu, d3 = v3 - mu;
            float q = d0 * d0 + d1 * d1 + d2 * d2 + d3 * d3;
            #pragma unroll
            for (int o = 16; o > 0; o >>= 1) q += __shfl_xor_sync(0xffffffffu, q, o);
            float rstd = rsqrtf(q * (1.0f / 128.0f) + 1e-5f);
            rp[lane]      = d0 * rstd * w0 + b0;
            rp[lane + 32] = d1 * rstd * w1 + b1;
            rp[lane + 64] = d2 * rstd * w2 + b2;
            rp[lane + 96] = d3 * rstd * w3 + b3;
        }
    }
    __syncthreads();

    float acc[32];
    #pragma unroll
    for (int r = 0; r < 32; r++) acc[r] = 0.0f;
    const float* wp = g_wT + tid;
    for (int d4 = 0; d4 < 128; d4 += 4) {
        float wa = wp[(d4 + 0) * WCOLS];
        float wb = wp[(d4 + 1) * WCOLS];
        float wc = wp[(d4 + 2) * WCOLS];
        float wd = wp[(d4 + 3) * WCOLS];
        #pragma unroll
        for (int r = 0; r < 32; r++) {
            float4 x = *(const float4*)(rows + r * 128 + d4);
            acc[r] += wa * x.x + wb * x.y + wc * x.z + wd * x.w;
        }
    }

    if (tid >= 512) {
        int e = tid - 512;
        #pragma unroll
        for (int r = 0; r < 32; r++) {
            float s = 1.0f / (1.0f + __expf(-acc[r]));
            g_gate[(size_t)(rowbase + r) * DDIM + e] = s;
        }
    }

    if (tid < 256) {
        #pragma unroll
        for (int r = 0; r < 32; r++) pstage[r * 256 + tid] = acc[r];
    }
    __syncthreads();

    if (tid >= 256 && tid < 512) {
        int h = tid - 256;
        #pragma unroll
        for (int r = 0; r < 32; r++) {
            float s = 1.0f / (1.0f + __expf(-acc[r]));
            acc[r] = s * pstage[r * 256 + h];
        }
    }
    __syncthreads();

    if (tid >= 256 && tid < 512) {
        int h = tid - 256;
        float* stg = (h < 128) ? rows : pstage;
        int hh = h & 127;
        #pragma unroll
        for (int r = 0; r < 32; r++) stg[r * 128 + ((hh + r) & 127)] = acc[r];
    }
    __syncthreads();

    for (int idx = tid; idx < 4096; idx += 640) {
        int h = idx >> 5, r = idx & 31;
        float lv = rows  [r * 128 + ((h + r) & 127)];
        float rv = pstage[r * 128 + ((h + r) & 127)];
        g_left [(size_t)h * NPAIR + rowbase + r] = lv;
        g_right[(size_t)h * NPAIR + rowbase + r] = rv;
    }
}

/* --------- stage 2: 128 batched GEMM-NT 512x512x512 via tf32 mma --------- */
__device__ __forceinline__ uint32_t f2tf(float x) {
    uint32_t r;
    asm("cvt.rna.tf32.f32 %0, %1;" : "=r"(r) : "f"(x));
    return r;
}

__device__ __forceinline__ void mma_tf32(float* c, const uint32_t* a, const uint32_t* b) {
    asm volatile("mma.sync.aligned.m16n8k8.row.col.f32.tf32.tf32.f32 "
                 "{%0,%1,%2,%3}, {%4,%5,%6,%7}, {%8,%9}, {%0,%1,%2,%3};"
                 : "+f"(c[0]), "+f"(c[1]), "+f"(c[2]), "+f"(c[3])
                 : "r"(a[0]), "r"(a[1]), "r"(a[2]), "r"(a[3]),
                   "r"(b[0]), "r"(b[1]));
}

/* smem tile: [row][k], 128 rows x 16 k, phys_k = k ^ (((row>>1)&3)<<2)      */
__device__ __forceinline__ int sw_addr(int row, int k) {
    return row * 16 + (k ^ (((row >> 1) & 3) << 2));
}

__global__ void __launch_bounds__(256) kgemm()
{
    __shared__ uint32_t As[128 * 16];
    __shared__ uint32_t Bs[128 * 16];

    const int d = blockIdx.z;
    const float* Ag = g_left  + (size_t)d * NPAIR + (size_t)blockIdx.y * 128 * 512;
    const float* Bg = g_right + (size_t)d * NPAIR + (size_t)blockIdx.x * 128 * 512;

    const int tid  = threadIdx.x;
    const int wid  = tid >> 5, lane = tid & 31;
    const int wm   = wid & 1;          /* 2 warps in m  -> 64 rows each */
    const int wn   = wid >> 1;         /* 4 warps in n  -> 32 cols each */
    const int g    = lane >> 2;        /* groupID        */
    const int t    = lane & 3;         /* thread in group */

    /* global load mapping: 2 float4 per tile per thread */
    const int lr0 = tid >> 2;                   /* rows 0..63   */
    const int lc4 = (tid & 3) << 2;             /* k offset 0..12 */

    float c[16][4];
    #pragma unroll
    for (int q = 0; q < 16; q++) { c[q][0] = 0; c[q][1] = 0; c[q][2] = 0; c[q][3] = 0; }

    uint4 ra[2], rb[2];

    /* preload chunk 0 */
    #pragma unroll
    for (int p = 0; p < 2; p++) {
        int r = lr0 + p * 64;
        float4 va = *(const float4*)(Ag + (size_t)r * 512 + lc4);
        float4 vb = *(const float4*)(Bg + (size_t)r * 512 + lc4);
        ra[p] = make_uint4(f2tf(va.x), f2tf(va.y), f2tf(va.z), f2tf(va.w));
        rb[p] = make_uint4(f2tf(vb.x), f2tf(vb.y), f2tf(vb.z), f2tf(vb.w));
    }

    for (int kt = 0; kt < 512; kt += 16) {
        __syncthreads();
        #pragma unroll
        for (int p = 0; p < 2; p++) {
            int r = lr0 + p * 64;
            int pk = lc4 ^ (((r >> 1) & 3) << 2);
            *(uint4*)&As[r * 16 + pk] = ra[p];
            *(uint4*)&Bs[r * 16 + pk] = rb[p];
        }
        __syncthreads();

        if (kt + 16 < 512) {
            #pragma unroll
            for (int p = 0; p < 2; p++) {
                int r = lr0 + p * 64;
                float4 va = *(const float4*)(Ag + (size_t)r * 512 + kt + 16 + lc4);
                float4 vb = *(const float4*)(Bg + (size_t)r * 512 + kt + 16 + lc4);
                ra[p] = make_uint4(f2tf(va.x), f2tf(va.y), f2tf(va.z), f2tf(va.w));
                rb[p] = make_uint4(f2tf(vb.x), f2tf(vb.y), f2tf(vb.z), f2tf(vb.w));
            }
        }

        #pragma unroll
        for (int ks = 0; ks < 16; ks += 8) {
            uint32_t a[4][4], b[4][2];
            #pragma unroll
            for (int m = 0; m < 4; m++) {
                int row = wm * 64 + m * 16 + g;
                a[m][0] = As[sw_addr(row,     ks + t)];
                a[m][1] = As[sw_addr(row + 8, ks + t)];
                a[m][2] = As[sw_addr(row,     ks + t + 4)];
                a[m][3] = As[sw_addr(row + 8, ks + t + 4)];
            }
            #pragma unroll
            for (int nt = 0; nt < 4; nt++) {
                int row = wn * 32 + nt * 8 + g;
                b[nt][0] = Bs[sw_addr(row, ks + t)];
                b[nt][1] = Bs[sw_addr(row, ks + t + 4)];
            }
            #pragma unroll
            for (int m = 0; m < 4; m++)
                #pragma unroll
                for (int nt = 0; nt < 4; nt++)
                    mma_tf32(c[m * 4 + nt], a[m], b[nt]);
        }
    }

    /* writeout: C[row][col], scaled by 1/512 */
    const float inv = 1.0f / 512.0f;
    float* C = g_outT + (size_t)d * NPAIR;
    const int rbase = blockIdx.y * 128 + wm * 64;
    const int cbase = blockIdx.x * 128 + wn * 32;
    #pragma unroll
    for (int m = 0; m < 4; m++) {
        #pragma unroll
        for (int nt = 0; nt < 4; nt++) {
            const float* cc = c[m * 4 + nt];
            int row = rbase + m * 16 + g;
            int col = cbase + nt * 8 + 2 * t;
            float2 v0 = make_float2(cc[0] * inv, cc[1] * inv);
            float2 v1 = make_float2(cc[2] * inv, cc[3] * inv);
            *(float2*)(C + (size_t)row * 512 + col)       = v0;
            *(float2*)(C + (size_t)(row + 8) * 512 + col) = v1;
        }
    }
}

/* --------- stage 3: LN over d + p_out projection + gate ------------------ */
__global__ void __launch_bounds__(256) kout(const float* __restrict__ lnw,
                                            const float* __restrict__ lnb,
                                            float* __restrict__ outp)
{
    __shared__ float o[64 * 129];   /* [j][d], padded */

    const int i = blockIdx.y;
    const int j0 = blockIdx.x * 64;
    const int tid = threadIdx.x;

    for (int idx = tid; idx < 64 * 128; idx += 256) {
        int dd = idx >> 6, j = idx & 63;
        o[j * 129 + dd] = g_outT[(size_t)dd * NPAIR + (size_t)i * 512 + j0 + j];
    }
    __syncthreads();

    const int wid = tid >> 5, lane = tid & 31;
    {
        float w0 = lnw[lane], w1 = lnw[lane + 32], w2 = lnw[lane + 64], w3 = lnw[lane + 96];
        float b0 = lnb[lane], b1 = lnb[lane + 32], b2 = lnb[lane + 64], b3 = lnb[lane + 96];
        for (int j = wid; j < 64; j += 8) {
            float* rp = o + j * 129;
            float v0 = rp[lane], v1 = rp[lane + 32], v2 = rp[lane + 64], v3 = rp[lane + 96];
            float s = v0 + v1 + v2 + v3;
            #pragma unroll
            for (int off = 16; off > 0; off >>= 1) s += __shfl_xor_sync(0xffffffffu, s, off);
            float mu = s * (1.0f / 128.0f);
            float d0 = v0 - mu, d1 = v1 - mu, d2 = v2 - mu, d3 = v3 - mu;
            float q = d0 * d0 + d1 * d1 + d2 * d2 + d3 * d3;
            #pragma unroll
            for (int off = 16; off > 0; off >>= 1) q += __shfl_xor_sync(0xffffffffu, q, off);
            float rstd = rsqrtf(q * (1.0f / 128.0f) + 1e-5f);
            rp[lane]      = d0 * rstd * w0 + b0;
            rp[lane + 32] = d1 * rstd * w1 + b1;
            rp[lane + 64] = d2 * rstd * w2 + b2;
            rp[lane + 96] = d3 * rstd * w3 + b3;
        }
    }
    __syncthreads();

    const int d = tid & 127, half = tid >> 7;
    for (int jc = half * 32; jc < half * 32 + 32; jc += 16) {
        float acc[16];
        #pragma unroll
        for (int r = 0; r < 16; r++) acc[r] = 0.0f;
        for (int h = 0; h < 128; h++) {
            float w = g_wOT[h * 128 + d];
            #pragma unroll
            for (int r = 0; r < 16; r++) acc[r] += w * o[(jc + r) * 129 + h];
        }
        #pragma unroll
        for (int r = 0; r < 16; r++) {
            size_t row = (size_t)i * 512 + j0 + jc + r;
            outp[row * 128 + d] = g_gate[row * 128 + d] * acc[r];
        }
    }
}

/* ------------------------------- launch ---------------------------------- */
extern "C" void kernel_launch(void* const* d_in, const int* in_sizes, int n_in,
                              void* d_out, int out_size)
{
    const float* pair     = (const float*)d_in[0];
    const float* ln_in_w  = (const float*)d_in[1];
    const float* ln_in_b  = (const float*)d_in[2];
    const float* p_in_w   = (const float*)d_in[3];
    const float* g_in_w   = (const float*)d_in[4];
    const float* ln_out_w = (const float*)d_in[5];
    const float* ln_out_b = (const float*)d_in[6];
    const float* p_out_w  = (const float*)d_in[7];
    const float* g_out_w  = (const float*)d_in[8];
    float* out = (float*)d_out;

    kprep<<<(DDIM * WCOLS + DDIM * DDIM + 255) / 256, 256>>>(p_in_w, g_in_w, g_out_w, p_out_w);
    kproj<<<NPAIR / 32, 640>>>(pair, ln_in_w, ln_in_b);
    kgemm<<<dim3(4, 4, 128), 256>>>();
    kout<<<dim3(8, 512), 256>>>(ln_out_w, ln_out_b, out);
}

// round 7
// speedup vs baseline: 2.0506x; 1.5777x over previous
#include <cuda_runtime.h>
#include <cstdint>
#include <cstddef>

#define NROW 512
#define DDIM 128
#define NPAIR (NROW * NROW)          /* 262144 rows */

/* -------- scratch (static device globals; no allocations allowed) -------- */
static __device__ float    g_left [(size_t)DDIM * NPAIR];   /* [d][i*512+k] */
static __device__ float    g_right[(size_t)DDIM * NPAIR];   /* [d][j*512+k] */
static __device__ float    g_gate [(size_t)NPAIR * DDIM];   /* [row][e]     */
static __device__ float    g_outT [(size_t)DDIM * NPAIR];   /* [d][i*512+j] */
static __device__ uint32_t g_xn   [(size_t)NPAIR * DDIM];   /* LN(pair) in tf32, [row][d] */
static __device__ uint32_t g_wC   [640 * DDIM];             /* reordered proj weights, tf32 [n][k] */
static __device__ float    g_wOT  [DDIM * DDIM];            /* [h][d] = p_out_w[d][h] */

/* ------------------------------ helpers ---------------------------------- */
__device__ __forceinline__ uint32_t f2tf(float x) {
    uint32_t r;
    asm("cvt.rna.tf32.f32 %0, %1;" : "=r"(r) : "f"(x));
    return r;
}

__device__ __forceinline__ void mma_tf32(float* c, const uint32_t* a, const uint32_t* b) {
    asm volatile("mma.sync.aligned.m16n8k8.row.col.f32.tf32.tf32.f32 "
                 "{%0,%1,%2,%3}, {%4,%5,%6,%7}, {%8,%9}, {%0,%1,%2,%3};"
                 : "+f"(c[0]), "+f"(c[1]), "+f"(c[2]), "+f"(c[3])
                 : "r"(a[0]), "r"(a[1]), "r"(a[2]), "r"(a[3]),
                   "r"(b[0]), "r"(b[1]));
}

__device__ __forceinline__ float sigf(float x) {
    return 1.0f / (1.0f + __expf(-x));
}

/* ------------------------- weight prep ----------------------------------- */
/* g_wC row r: tile t=r>>7, u=r&127.  t<4: u<64 -> p_in col t*64+u,           */
/*             u>=64 -> g_in col t*64+u-64 (so p/g pairs are CTA-local).     */
/* t==4: g_out rows.  Stored tf32, [n][k] layout.                            */
__global__ void kprep(const float* __restrict__ p_in_w, const float* __restrict__ g_in_w,
                      const float* __restrict__ g_out_w, const float* __restrict__ p_out_w)
{
    int idx = blockIdx.x * blockDim.x + threadIdx.x;
    if (idx < 640 * 128) {
        int r = idx >> 7, k = idx & 127;
        int t = r >> 7, u = r & 127;
        float v;
        if (t < 4) v = (u < 64) ? p_in_w[(t * 64 + u) * 128 + k]
                                : g_in_w[(t * 64 + u - 64) * 128 + k];
        else       v = g_out_w[u * 128 + k];
        g_wC[idx] = f2tf(v);
    } else if (idx < 640 * 128 + 128 * 128) {
        int k2 = idx - 640 * 128;
        int h = k2 >> 7, d = k2 & 127;
        g_wOT[k2] = p_out_w[d * 128 + h];
    }
}

/* --------- stage 0: LayerNorm -> tf32, row-major ------------------------- */
__global__ void __launch_bounds__(256) kln(const float* __restrict__ pair,
                                           const float* __restrict__ lnw,
                                           const float* __restrict__ lnb)
{
    const int wid = threadIdx.x >> 5, lane = threadIdx.x & 31;
    const size_t row = (size_t)blockIdx.x * 8 + wid;

    float4 x = *(const float4*)(pair + row * 128 + lane * 4);
    float s = x.x + x.y + x.z + x.w;
    #pragma unroll
    for (int o = 16; o > 0; o >>= 1) s += __shfl_xor_sync(0xffffffffu, s, o);
    float mu = s * (1.0f / 128.0f);
    float d0 = x.x - mu, d1 = x.y - mu, d2 = x.z - mu, d3 = x.w - mu;
    float q = d0 * d0 + d1 * d1 + d2 * d2 + d3 * d3;
    #pragma unroll
    for (int o = 16; o > 0; o >>= 1) q += __shfl_xor_sync(0xffffffffu, q, o);
    float rstd = rsqrtf(q * (1.0f / 128.0f) + 1e-5f);

    float4 w = *(const float4*)(lnw + lane * 4);
    float4 b = *(const float4*)(lnb + lane * 4);
    uint4 o4;
    o4.x = f2tf(d0 * rstd * w.x + b.x);
    o4.y = f2tf(d1 * rstd * w.y + b.y);
    o4.z = f2tf(d2 * rstd * w.z + b.z);
    o4.w = f2tf(d3 * rstd * w.w + b.w);
    *(uint4*)(g_xn + row * 128 + lane * 4) = o4;
}

/* --------- stage 1: projection GEMM (tf32 mma) + sigmoid fusion ---------- */
/* 32-wide smem rows, phys_k = k ^ ((row&7)<<2)                              */
__device__ __forceinline__ int sw32(int row, int k) {
    return row * 32 + (k ^ ((row & 7) << 2));
}

__global__ void __launch_bounds__(256) kproj2()
{
    __shared__ uint32_t sbuf[128 * 65];          /* 33.3 KB union            */
    uint32_t* Xs = sbuf;                          /* 128 x 32                 */
    uint32_t* Ws = sbuf + 4096;                   /* 128 x 32                 */
    float*    G  = (float*)sbuf;                  /* epilogue: 128 x 65       */

    const int bx = blockIdx.x;                    /* n-tile 0..4              */
    const size_t rowbase = (size_t)blockIdx.y * 128;

    const int tid = threadIdx.x;
    const int wid = tid >> 5, lane = tid & 31;
    const int wm = wid & 1, wn = wid >> 1;
    const int g = lane >> 2, t = lane & 3;

    float c[16][4];
    #pragma unroll
    for (int q = 0; q < 16; q++) { c[q][0] = 0; c[q][1] = 0; c[q][2] = 0; c[q][3] = 0; }

    for (int kc = 0; kc < 128; kc += 32) {
        __syncthreads();
        #pragma unroll
        for (int p = 0; p < 4; p++) {
            int s = tid + p * 256;
            int r = s >> 3, k4 = (s & 7) << 2;
            int phys = k4 ^ ((r & 7) << 2);
            *(uint4*)&Xs[r * 32 + phys] =
                *(const uint4*)(g_xn + (rowbase + r) * 128 + kc + k4);
            *(uint4*)&Ws[r * 32 + phys] =
                *(const uint4*)(g_wC + (size_t)(bx * 128 + r) * 128 + kc + k4);
        }
        __syncthreads();

        #pragma unroll
        for (int ks = 0; ks < 32; ks += 8) {
            uint32_t a[4][4], b[4][2];
            #pragma unroll
            for (int m = 0; m < 4; m++) {
                int row = wm * 64 + m * 16 + g;
                a[m][0] = Xs[sw32(row,     ks + t)];
                a[m][1] = Xs[sw32(row + 8, ks + t)];
                a[m][2] = Xs[sw32(row,     ks + t + 4)];
                a[m][3] = Xs[sw32(row + 8, ks + t + 4)];
            }
            #pragma unroll
            for (int nt = 0; nt < 4; nt++) {
                int nr = wn * 32 + nt * 8 + g;
                b[nt][0] = Ws[sw32(nr, ks + t)];
                b[nt][1] = Ws[sw32(nr, ks + t + 4)];
            }
            #pragma unroll
            for (int m = 0; m < 4; m++)
                #pragma unroll
                for (int nt = 0; nt < 4; nt++)
                    mma_tf32(c[m * 4 + nt], a[m], b[nt]);
        }
    }
    __syncthreads();

    if (bx < 4) {
        /* p/g tile: cols 0..63 = p, 64..127 = g (matching h pairs) */
        if (wn >= 2) {  /* g warps: stage sigmoid(g) */
            #pragma unroll
            for (int m = 0; m < 4; m++)
                #pragma unroll
                for (int nt = 0; nt < 4; nt++) {
                    int row = wm * 64 + m * 16 + g;
                    int col = wn * 32 + nt * 8 + 2 * t - 64;
                    const float* cc = c[m * 4 + nt];
                    G[row * 65 + col]           = sigf(cc[0]);
                    G[row * 65 + col + 1]       = sigf(cc[1]);
                    G[(row + 8) * 65 + col]     = sigf(cc[2]);
                    G[(row + 8) * 65 + col + 1] = sigf(cc[3]);
                }
        }
        __syncthreads();
        if (wn < 2) {   /* p warps: multiply in place */
            #pragma unroll
            for (int m = 0; m < 4; m++)
                #pragma unroll
                for (int nt = 0; nt < 4; nt++) {
                    int row = wm * 64 + m * 16 + g;
                    int col = wn * 32 + nt * 8 + 2 * t;
                    const float* cc = c[m * 4 + nt];
                    G[row * 65 + col]           *= cc[0];
                    G[row * 65 + col + 1]       *= cc[1];
                    G[(row + 8) * 65 + col]     *= cc[2];
                    G[(row + 8) * 65 + col + 1] *= cc[3];
                }
        }
        __syncthreads();
        /* coalesced channel-major writeout */
        #pragma unroll
        for (int p = 0; p < 32; p++) {
            int s = tid + p * 256;
            int col = s >> 7, row = s & 127;
            int hg = bx * 64 + col;
            float v = G[row * 65 + col];
            float* dst = (hg < 128) ? g_left : g_right;
            dst[(size_t)(hg & 127) * NPAIR + rowbase + row] = v;
        }
    } else {
        /* gate tile: sigmoid all 128 cols, row-major writeout in halves */
        if (wn < 2) {
            #pragma unroll
            for (int m = 0; m < 4; m++)
                #pragma unroll
                for (int nt = 0; nt < 4; nt++) {
                    int row = wm * 64 + m * 16 + g;
                    int col = wn * 32 + nt * 8 + 2 * t;
                    const float* cc = c[m * 4 + nt];
                    G[row * 65 + col]           = sigf(cc[0]);
                    G[row * 65 + col + 1]       = sigf(cc[1]);
                    G[(row + 8) * 65 + col]     = sigf(cc[2]);
                    G[(row + 8) * 65 + col + 1] = sigf(cc[3]);
                }
        }
        __syncthreads();
        #pragma unroll
        for (int p = 0; p < 32; p++) {
            int s = tid + p * 256;
            int row = s >> 6, e = s & 63;
            g_gate[(rowbase + row) * 128 + e] = G[row * 65 + e];
        }
        __syncthreads();
        if (wn >= 2) {
            #pragma unroll
            for (int m = 0; m < 4; m++)
                #pragma unroll
                for (int nt = 0; nt < 4; nt++) {
                    int row = wm * 64 + m * 16 + g;
                    int col = wn * 32 + nt * 8 + 2 * t - 64;
                    const float* cc = c[m * 4 + nt];
                    G[row * 65 + col]           = sigf(cc[0]);
                    G[row * 65 + col + 1]       = sigf(cc[1]);
                    G[(row + 8) * 65 + col]     = sigf(cc[2]);
                    G[(row + 8) * 65 + col + 1] = sigf(cc[3]);
                }
        }
        __syncthreads();
        #pragma unroll
        for (int p = 0; p < 32; p++) {
            int s = tid + p * 256;
            int row = s >> 6, e = s & 63;
            g_gate[(rowbase + row) * 128 + 64 + e] = G[row * 65 + e];
        }
    }
}

/* --------- stage 2: 128 batched GEMM-NT 512x512x512 via tf32 mma --------- */
__device__ __forceinline__ int sw_addr(int row, int k) {
    return row * 16 + (k ^ (((row >> 1) & 3) << 2));
}

__global__ void __launch_bounds__(256) kgemm()
{
    __shared__ uint32_t As[128 * 16];
    __shared__ uint32_t Bs[128 * 16];

    const int d = blockIdx.z;
    const float* Ag = g_left  + (size_t)d * NPAIR + (size_t)blockIdx.y * 128 * 512;
    const float* Bg = g_right + (size_t)d * NPAIR + (size_t)blockIdx.x * 128 * 512;

    const int tid  = threadIdx.x;
    const int wid  = tid >> 5, lane = tid & 31;
    const int wm   = wid & 1;
    const int wn   = wid >> 1;
    const int g    = lane >> 2;
    const int t    = lane & 3;

    const int lr0 = tid >> 2;
    const int lc4 = (tid & 3) << 2;

    float c[16][4];
    #pragma unroll
    for (int q = 0; q < 16; q++) { c[q][0] = 0; c[q][1] = 0; c[q][2] = 0; c[q][3] = 0; }

    uint4 ra[2], rb[2];

    #pragma unroll
    for (int p = 0; p < 2; p++) {
        int r = lr0 + p * 64;
        float4 va = *(const float4*)(Ag + (size_t)r * 512 + lc4);
        float4 vb = *(const float4*)(Bg + (size_t)r * 512 + lc4);
        ra[p] = make_uint4(f2tf(va.x), f2tf(va.y), f2tf(va.z), f2tf(va.w));
        rb[p] = make_uint4(f2tf(vb.x), f2tf(vb.y), f2tf(vb.z), f2tf(vb.w));
    }

    for (int kt = 0; kt < 512; kt += 16) {
        __syncthreads();
        #pragma unroll
        for (int p = 0; p < 2; p++) {
            int r = lr0 + p * 64;
            int pk = lc4 ^ (((r >> 1) & 3) << 2);
            *(uint4*)&As[r * 16 + pk] = ra[p];
            *(uint4*)&Bs[r * 16 + pk] = rb[p];
        }
        __syncthreads();

        if (kt + 16 < 512) {
            #pragma unroll
            for (int p = 0; p < 2; p++) {
                int r = lr0 + p * 64;
                float4 va = *(const float4*)(Ag + (size_t)r * 512 + kt + 16 + lc4);
                float4 vb = *(const float4*)(Bg + (size_t)r * 512 + kt + 16 + lc4);
                ra[p] = make_uint4(f2tf(va.x), f2tf(va.y), f2tf(va.z), f2tf(va.w));
                rb[p] = make_uint4(f2tf(vb.x), f2tf(vb.y), f2tf(vb.z), f2tf(vb.w));
            }
        }

        #pragma unroll
        for (int ks = 0; ks < 16; ks += 8) {
            uint32_t a[4][4], b[4][2];
            #pragma unroll
            for (int m = 0; m < 4; m++) {
                int row = wm * 64 + m * 16 + g;
                a[m][0] = As[sw_addr(row,     ks + t)];
                a[m][1] = As[sw_addr(row + 8, ks + t)];
                a[m][2] = As[sw_addr(row,     ks + t + 4)];
                a[m][3] = As[sw_addr(row + 8, ks + t + 4)];
            }
            #pragma unroll
            for (int nt = 0; nt < 4; nt++) {
                int row = wn * 32 + nt * 8 + g;
                b[nt][0] = Bs[sw_addr(row, ks + t)];
                b[nt][1] = Bs[sw_addr(row, ks + t + 4)];
            }
            #pragma unroll
            for (int m = 0; m < 4; m++)
                #pragma unroll
                for (int nt = 0; nt < 4; nt++)
                    mma_tf32(c[m * 4 + nt], a[m], b[nt]);
        }
    }

    const float inv = 1.0f / 512.0f;
    float* C = g_outT + (size_t)d * NPAIR;
    const int rbase = blockIdx.y * 128 + wm * 64;
    const int cbase = blockIdx.x * 128 + wn * 32;
    #pragma unroll
    for (int m = 0; m < 4; m++) {
        #pragma unroll
        for (int nt = 0; nt < 4; nt++) {
            const float* cc = c[m * 4 + nt];
            int row = rbase + m * 16 + g;
            int col = cbase + nt * 8 + 2 * t;
            float2 v0 = make_float2(cc[0] * inv, cc[1] * inv);
            float2 v1 = make_float2(cc[2] * inv, cc[3] * inv);
            *(float2*)(C + (size_t)row * 512 + col)       = v0;
            *(float2*)(C + (size_t)(row + 8) * 512 + col) = v1;
        }
    }
}

/* --------- stage 3: LN over d + p_out projection + gate ------------------ */
__global__ void __launch_bounds__(256) kout(const float* __restrict__ lnw,
                                            const float* __restrict__ lnb,
                                            float* __restrict__ outp)
{
    __shared__ float o[64 * 129];

    const int i = blockIdx.y;
    const int j0 = blockIdx.x * 64;
    const int tid = threadIdx.x;

    for (int idx = tid; idx < 64 * 128; idx += 256) {
        int dd = idx >> 6, j = idx & 63;
        o[j * 129 + dd] = g_outT[(size_t)dd * NPAIR + (size_t)i * 512 + j0 + j];
    }
    __syncthreads();

    const int wid = tid >> 5, lane = tid & 31;
    {
        float w0 = lnw[lane], w1 = lnw[lane + 32], w2 = lnw[lane + 64], w3 = lnw[lane + 96];
        float b0 = lnb[lane], b1 = lnb[lane + 32], b2 = lnb[lane + 64], b3 = lnb[lane + 96];
        for (int j = wid; j < 64; j += 8) {
            float* rp = o + j * 129;
            float v0 = rp[lane], v1 = rp[lane + 32], v2 = rp[lane + 64], v3 = rp[lane + 96];
            float s = v0 + v1 + v2 + v3;
            #pragma unroll
            for (int off = 16; off > 0; off >>= 1) s += __shfl_xor_sync(0xffffffffu, s, off);
            float mu = s * (1.0f / 128.0f);
            float d0 = v0 - mu, d1 = v1 - mu, d2 = v2 - mu, d3 = v3 - mu;
            float q = d0 * d0 + d1 * d1 + d2 * d2 + d3 * d3;
            #pragma unroll
            for (int off = 16; off > 0; off >>= 1) q += __shfl_xor_sync(0xffffffffu, q, off);
            float rstd = rsqrtf(q * (1.0f / 128.0f) + 1e-5f);
            rp[lane]      = d0 * rstd * w0 + b0;
            rp[lane + 32] = d1 * rstd * w1 + b1;
            rp[lane + 64] = d2 * rstd * w2 + b2;
            rp[lane + 96] = d3 * rstd * w3 + b3;
        }
    }
    __syncthreads();

    const int d = tid & 127, half = tid >> 7;
    for (int jc = half * 32; jc < half * 32 + 32; jc += 16) {
        float acc[16];
        #pragma unroll
        for (int r = 0; r < 16; r++) acc[r] = 0.0f;
        for (int h = 0; h < 128; h++) {
            float w = g_wOT[h * 128 + d];
            #pragma unroll
            for (int r = 0; r < 16; r++) acc[r] += w * o[(jc + r) * 129 + h];
        }
        #pragma unroll
        for (int r = 0; r < 16; r++) {
            size_t row = (size_t)i * 512 + j0 + jc + r;
            outp[row * 128 + d] = g_gate[row * 128 + d] * acc[r];
        }
    }
}

/* ------------------------------- launch ---------------------------------- */
extern "C" void kernel_launch(void* const* d_in, const int* in_sizes, int n_in,
                              void* d_out, int out_size)
{
    const float* pair     = (const float*)d_in[0];
    const float* ln_in_w  = (const float*)d_in[1];
    const float* ln_in_b  = (const float*)d_in[2];
    const float* p_in_w   = (const float*)d_in[3];
    const float* g_in_w   = (const float*)d_in[4];
    const float* ln_out_w = (const float*)d_in[5];
    const float* ln_out_b = (const float*)d_in[6];
    const float* p_out_w  = (const float*)d_in[7];
    const float* g_out_w  = (const float*)d_in[8];
    float* out = (float*)d_out;

    kprep<<<(640 * 128 + 128 * 128 + 255) / 256, 256>>>(p_in_w, g_in_w, g_out_w, p_out_w);
    kln<<<NPAIR / 8, 256>>>(pair, ln_in_w, ln_in_b);
    kproj2<<<dim3(5, 2048), 256>>>();
    kgemm<<<dim3(4, 4, 128), 256>>>();
    kout<<<dim3(8, 512), 256>>>(ln_out_w, ln_out_b, out);
}

// round 8
// speedup vs baseline: 2.8896x; 1.4092x over previous
#include <cuda_runtime.h>
#include <cstdint>
#include <cstddef>

#define NROW 512
#define DDIM 128
#define NPAIR (NROW * NROW)          /* 262144 rows */

/* -------- scratch (static device globals; no allocations allowed) -------- */
static __device__ float    g_left [(size_t)DDIM * NPAIR];   /* tf32 bits, [d][i*512+k] */
static __device__ float    g_right[(size_t)DDIM * NPAIR];   /* tf32 bits, [d][j*512+k] */
static __device__ float    g_gate [(size_t)NPAIR * DDIM];   /* fp32, [row][e] */
static __device__ float    g_outT [(size_t)DDIM * NPAIR];   /* fp32, [d][i*512+j] */
static __device__ uint32_t g_xn   [(size_t)NPAIR * DDIM];   /* LN(pair) tf32, [row][d] */
static __device__ uint32_t g_wC   [640 * DDIM];             /* proj weights tf32 [n][k] */
static __device__ uint32_t g_wO   [DDIM * DDIM];            /* p_out_w tf32 [d][h] */

/* ------------------------------ helpers ---------------------------------- */
__device__ __forceinline__ uint32_t f2tf(float x) {
    uint32_t r;
    asm("cvt.rna.tf32.f32 %0, %1;" : "=r"(r) : "f"(x));
    return r;
}

__device__ __forceinline__ void mma_tf32(float* c, const uint32_t* a, const uint32_t* b) {
    asm volatile("mma.sync.aligned.m16n8k8.row.col.f32.tf32.tf32.f32 "
                 "{%0,%1,%2,%3}, {%4,%5,%6,%7}, {%8,%9}, {%0,%1,%2,%3};"
                 : "+f"(c[0]), "+f"(c[1]), "+f"(c[2]), "+f"(c[3])
                 : "r"(a[0]), "r"(a[1]), "r"(a[2]), "r"(a[3]),
                   "r"(b[0]), "r"(b[1]));
}

__device__ __forceinline__ float sigf(float x) {
    return 1.0f / (1.0f + __expf(-x));
}

#define CP_ASYNC16(dst_u32, src_ptr) \
    asm volatile("cp.async.cg.shared.global [%0], [%1], 16;" :: "r"(dst_u32), "l"(src_ptr) : "memory")
#define CP_COMMIT() asm volatile("cp.async.commit_group;" ::: "memory")
#define CP_WAIT1()  asm volatile("cp.async.wait_group 1;" ::: "memory")

/* ------------------------- weight prep ----------------------------------- */
__global__ void kprep(const float* __restrict__ p_in_w, const float* __restrict__ g_in_w,
                      const float* __restrict__ g_out_w, const float* __restrict__ p_out_w)
{
    int idx = blockIdx.x * blockDim.x + threadIdx.x;
    if (idx < 640 * 128) {
        int r = idx >> 7, k = idx & 127;
        int t = r >> 7, u = r & 127;
        float v;
        if (t < 4) v = (u < 64) ? p_in_w[(t * 64 + u) * 128 + k]
                                : g_in_w[(t * 64 + u - 64) * 128 + k];
        else       v = g_out_w[u * 128 + k];
        g_wC[idx] = f2tf(v);
    } else if (idx < 640 * 128 + 128 * 128) {
        int k2 = idx - 640 * 128;
        g_wO[k2] = f2tf(p_out_w[k2]);   /* [d][h], same layout as torch weight */
    }
}

/* --------- stage 0: LayerNorm -> tf32, row-major ------------------------- */
__global__ void __launch_bounds__(256) kln(const float* __restrict__ pair,
                                           const float* __restrict__ lnw,
                                           const float* __restrict__ lnb)
{
    const int wid = threadIdx.x >> 5, lane = threadIdx.x & 31;
    const size_t row = (size_t)blockIdx.x * 8 + wid;

    float4 x = *(const float4*)(pair + row * 128 + lane * 4);
    float s = x.x + x.y + x.z + x.w;
    #pragma unroll
    for (int o = 16; o > 0; o >>= 1) s += __shfl_xor_sync(0xffffffffu, s, o);
    float mu = s * (1.0f / 128.0f);
    float d0 = x.x - mu, d1 = x.y - mu, d2 = x.z - mu, d3 = x.w - mu;
    float q = d0 * d0 + d1 * d1 + d2 * d2 + d3 * d3;
    #pragma unroll
    for (int o = 16; o > 0; o >>= 1) q += __shfl_xor_sync(0xffffffffu, q, o);
    float rstd = rsqrtf(q * (1.0f / 128.0f) + 1e-5f);

    float4 w = *(const float4*)(lnw + lane * 4);
    float4 b = *(const float4*)(lnb + lane * 4);
    uint4 o4;
    o4.x = f2tf(d0 * rstd * w.x + b.x);
    o4.y = f2tf(d1 * rstd * w.y + b.y);
    o4.z = f2tf(d2 * rstd * w.z + b.z);
    o4.w = f2tf(d3 * rstd * w.w + b.w);
    *(uint4*)(g_xn + row * 128 + lane * 4) = o4;
}

/* --------- stage 1: projection GEMM (tf32 mma) + sigmoid fusion ---------- */
__device__ __forceinline__ int sw32(int row, int k) {
    return row * 32 + (k ^ ((row & 7) << 2));
}

__global__ void __launch_bounds__(256) kproj2()
{
    __shared__ uint32_t sbuf[128 * 65];
    uint32_t* Xs = sbuf;
    uint32_t* Ws = sbuf + 4096;
    float*    G  = (float*)sbuf;

    const int bx = blockIdx.x;
    const size_t rowbase = (size_t)blockIdx.y * 128;

    const int tid = threadIdx.x;
    const int wid = tid >> 5, lane = tid & 31;
    const int wm = wid & 1, wn = wid >> 1;
    const int g = lane >> 2, t = lane & 3;

    float c[16][4];
    #pragma unroll
    for (int q = 0; q < 16; q++) { c[q][0] = 0; c[q][1] = 0; c[q][2] = 0; c[q][3] = 0; }

    for (int kc = 0; kc < 128; kc += 32) {
        __syncthreads();
        #pragma unroll
        for (int p = 0; p < 4; p++) {
            int s = tid + p * 256;
            int r = s >> 3, k4 = (s & 7) << 2;
            int phys = k4 ^ ((r & 7) << 2);
            *(uint4*)&Xs[r * 32 + phys] =
                *(const uint4*)(g_xn + (rowbase + r) * 128 + kc + k4);
            *(uint4*)&Ws[r * 32 + phys] =
                *(const uint4*)(g_wC + (size_t)(bx * 128 + r) * 128 + kc + k4);
        }
        __syncthreads();

        #pragma unroll
        for (int ks = 0; ks < 32; ks += 8) {
            uint32_t a[4][4], b[4][2];
            #pragma unroll
            for (int m = 0; m < 4; m++) {
                int row = wm * 64 + m * 16 + g;
                a[m][0] = Xs[sw32(row,     ks + t)];
                a[m][1] = Xs[sw32(row + 8, ks + t)];
                a[m][2] = Xs[sw32(row,     ks + t + 4)];
                a[m][3] = Xs[sw32(row + 8, ks + t + 4)];
            }
            #pragma unroll
            for (int nt = 0; nt < 4; nt++) {
                int nr = wn * 32 + nt * 8 + g;
                b[nt][0] = Ws[sw32(nr, ks + t)];
                b[nt][1] = Ws[sw32(nr, ks + t + 4)];
            }
            #pragma unroll
            for (int m = 0; m < 4; m++)
                #pragma unroll
                for (int nt = 0; nt < 4; nt++)
                    mma_tf32(c[m * 4 + nt], a[m], b[nt]);
        }
    }
    __syncthreads();

    if (bx < 4) {
        if (wn >= 2) {
            #pragma unroll
            for (int m = 0; m < 4; m++)
                #pragma unroll
                for (int nt = 0; nt < 4; nt++) {
                    int row = wm * 64 + m * 16 + g;
                    int col = wn * 32 + nt * 8 + 2 * t - 64;
                    const float* cc = c[m * 4 + nt];
                    G[row * 65 + col]           = sigf(cc[0]);
                    G[row * 65 + col + 1]       = sigf(cc[1]);
                    G[(row + 8) * 65 + col]     = sigf(cc[2]);
                    G[(row + 8) * 65 + col + 1] = sigf(cc[3]);
                }
        }
        __syncthreads();
        if (wn < 2) {
            #pragma unroll
            for (int m = 0; m < 4; m++)
                #pragma unroll
                for (int nt = 0; nt < 4; nt++) {
                    int row = wm * 64 + m * 16 + g;
                    int col = wn * 32 + nt * 8 + 2 * t;
                    const float* cc = c[m * 4 + nt];
                    G[row * 65 + col]           *= cc[0];
                    G[row * 65 + col + 1]       *= cc[1];
                    G[(row + 8) * 65 + col]     *= cc[2];
                    G[(row + 8) * 65 + col + 1] *= cc[3];
                }
        }
        __syncthreads();
        /* channel-major writeout, rounded to tf32-at-rest for kgemm */
        #pragma unroll
        for (int p = 0; p < 32; p++) {
            int s = tid + p * 256;
            int col = s >> 7, row = s & 127;
            int hg = bx * 64 + col;
            float v = G[row * 65 + col];
            float* dst = (hg < 128) ? g_left : g_right;
            dst[(size_t)(hg & 127) * NPAIR + rowbase + row] = __uint_as_float(f2tf(v));
        }
    } else {
        if (wn < 2) {
            #pragma unroll
            for (int m = 0; m < 4; m++)
                #pragma unroll
                for (int nt = 0; nt < 4; nt++) {
                    int row = wm * 64 + m * 16 + g;
                    int col = wn * 32 + nt * 8 + 2 * t;
                    const float* cc = c[m * 4 + nt];
                    G[row * 65 + col]           = sigf(cc[0]);
                    G[row * 65 + col + 1]       = sigf(cc[1]);
                    G[(row + 8) * 65 + col]     = sigf(cc[2]);
                    G[(row + 8) * 65 + col + 1] = sigf(cc[3]);
                }
        }
        __syncthreads();
        #pragma unroll
        for (int p = 0; p < 32; p++) {
            int s = tid + p * 256;
            int row = s >> 6, e = s & 63;
            g_gate[(rowbase + row) * 128 + e] = G[row * 65 + e];
        }
        __syncthreads();
        if (wn >= 2) {
            #pragma unroll
            for (int m = 0; m < 4; m++)
                #pragma unroll
                for (int nt = 0; nt < 4; nt++) {
                    int row = wm * 64 + m * 16 + g;
                    int col = wn * 32 + nt * 8 + 2 * t - 64;
                    const float* cc = c[m * 4 + nt];
                    G[row * 65 + col]           = sigf(cc[0]);
                    G[row * 65 + col + 1]       = sigf(cc[1]);
                    G[(row + 8) * 65 + col]     = sigf(cc[2]);
                    G[(row + 8) * 65 + col + 1] = sigf(cc[3]);
                }
        }
        __syncthreads();
        #pragma unroll
        for (int p = 0; p < 32; p++) {
            int s = tid + p * 256;
            int row = s >> 6, e = s & 63;
            g_gate[(rowbase + row) * 128 + 64 + e] = G[row * 65 + e];
        }
    }
}

/* --------- stage 2: 128 batched GEMM-NT 512x512x512, cp.async 3-stage ---- */
__device__ __forceinline__ int sw_addr(int row, int k) {
    return row * 16 + (k ^ (((row >> 1) & 3) << 2));
}

__global__ void __launch_bounds__(256) kgemm()
{
    __shared__ uint32_t As[3 * 2048];   /* 24 KB */
    __shared__ uint32_t Bs[3 * 2048];   /* 24 KB */

    const int d = blockIdx.z;
    const float* Ag = g_left  + (size_t)d * NPAIR + (size_t)blockIdx.y * 128 * 512;
    const float* Bg = g_right + (size_t)d * NPAIR + (size_t)blockIdx.x * 128 * 512;

    const int tid  = threadIdx.x;
    const int wid  = tid >> 5, lane = tid & 31;
    const int wm   = wid & 1;
    const int wn   = wid >> 1;
    const int g    = lane >> 2;
    const int t    = lane & 3;

    const int lr0 = tid >> 2;                 /* rows 0..63 (+64)      */
    const int lc4 = (tid & 3) << 2;           /* k offset 0/4/8/12     */
    const int pk  = lc4 ^ (((lr0 >> 1) & 3) << 2);   /* same for lr0+64 */

    const unsigned aBase = (unsigned)__cvta_generic_to_shared(As);
    const unsigned bBase = (unsigned)__cvta_generic_to_shared(Bs);
    const unsigned off0 = (unsigned)(lr0 * 16 + pk) * 4u;
    const unsigned off1 = (unsigned)((lr0 + 64) * 16 + pk) * 4u;

    float c[16][4];
    #pragma unroll
    for (int q = 0; q < 16; q++) { c[q][0] = 0; c[q][1] = 0; c[q][2] = 0; c[q][3] = 0; }

    /* prologue: chunks 0,1 */
    #pragma unroll
    for (int pc = 0; pc < 2; pc++) {
        const float* as = Ag + (size_t)lr0 * 512 + pc * 16 + lc4;
        const float* bs = Bg + (size_t)lr0 * 512 + pc * 16 + lc4;
        unsigned so = (unsigned)pc * 8192u;
        CP_ASYNC16(aBase + so + off0, as);
        CP_ASYNC16(aBase + so + off1, as + 64 * 512);
        CP_ASYNC16(bBase + so + off0, bs);
        CP_ASYNC16(bBase + so + off1, bs + 64 * 512);
        CP_COMMIT();
    }

    for (int cch = 0; cch < 32; cch++) {
        CP_WAIT1();
        __syncthreads();

        if (cch < 30) {
            int nc = cch + 2;
            const float* as = Ag + (size_t)lr0 * 512 + nc * 16 + lc4;
            const float* bs = Bg + (size_t)lr0 * 512 + nc * 16 + lc4;
            unsigned so = (unsigned)(nc % 3) * 8192u;
            CP_ASYNC16(aBase + so + off0, as);
            CP_ASYNC16(aBase + so + off1, as + 64 * 512);
            CP_ASYNC16(bBase + so + off0, bs);
            CP_ASYNC16(bBase + so + off1, bs + 64 * 512);
        }
        CP_COMMIT();

        const uint32_t* Asc = As + (cch % 3) * 2048;
        const uint32_t* Bsc = Bs + (cch % 3) * 2048;
        #pragma unroll
        for (int ks = 0; ks < 16; ks += 8) {
            uint32_t a[4][4], b[4][2];
            #pragma unroll
            for (int m = 0; m < 4; m++) {
                int row = wm * 64 + m * 16 + g;
                a[m][0] = Asc[sw_addr(row,     ks + t)];
                a[m][1] = Asc[sw_addr(row + 8, ks + t)];
                a[m][2] = Asc[sw_addr(row,     ks + t + 4)];
                a[m][3] = Asc[sw_addr(row + 8, ks + t + 4)];
            }
            #pragma unroll
            for (int nt = 0; nt < 4; nt++) {
                int row = wn * 32 + nt * 8 + g;
                b[nt][0] = Bsc[sw_addr(row, ks + t)];
                b[nt][1] = Bsc[sw_addr(row, ks + t + 4)];
            }
            #pragma unroll
            for (int m = 0; m < 4; m++)
                #pragma unroll
                for (int nt = 0; nt < 4; nt++)
                    mma_tf32(c[m * 4 + nt], a[m], b[nt]);
        }
    }

    const float inv = 1.0f / 512.0f;
    float* C = g_outT + (size_t)d * NPAIR;
    const int rbase = blockIdx.y * 128 + wm * 64;
    const int cbase = blockIdx.x * 128 + wn * 32;
    #pragma unroll
    for (int m = 0; m < 4; m++) {
        #pragma unroll
        for (int nt = 0; nt < 4; nt++) {
            const float* cc = c[m * 4 + nt];
            int row = rbase + m * 16 + g;
            int col = cbase + nt * 8 + 2 * t;
            float2 v0 = make_float2(cc[0] * inv, cc[1] * inv);
            float2 v1 = make_float2(cc[2] * inv, cc[3] * inv);
            *(float2*)(C + (size_t)row * 512 + col)       = v0;
            *(float2*)(C + (size_t)(row + 8) * 512 + col) = v1;
        }
    }
}

/* --------- stage 3: LN over d + p_out projection (tf32 mma) + gate ------- */
__global__ void __launch_bounds__(256) kout(const float* __restrict__ lnw,
                                            const float* __restrict__ lnb,
                                            float* __restrict__ outp)
{
    __shared__ uint32_t os[64 * 128];   /* 32KB: [j][h ^ ((j&7)<<2)] tf32 after LN */
    __shared__ uint32_t Wk[128 * 32];   /* 16KB: W chunk [d][k ^ ((d&7)<<2)]      */

    const int i = blockIdx.y;
    const int j0 = blockIdx.x * 64;
    const int tid = threadIdx.x;
    const int wid = tid >> 5, lane = tid & 31;

    /* load out tile [j][d] (swizzled) */
    for (int idx = tid; idx < 64 * 128; idx += 256) {
        int dd = idx >> 6, j = idx & 63;
        os[j * 128 + (dd ^ ((j & 7) << 2))] =
            __float_as_uint(g_outT[(size_t)dd * NPAIR + (size_t)i * 512 + j0 + j]);
    }
    __syncthreads();

    /* LayerNorm over d (fp32), write back tf32 bits */
    {
        float w0 = lnw[lane], w1 = lnw[lane + 32], w2 = lnw[lane + 64], w3 = lnw[lane + 96];
        float b0 = lnb[lane], b1 = lnb[lane + 32], b2 = lnb[lane + 64], b3 = lnb[lane + 96];
        for (int j = wid; j < 64; j += 8) {
            int sw = (j & 7) << 2;
            uint32_t* rp = os + j * 128;
            float v0 = __uint_as_float(rp[lane ^ sw]);
            float v1 = __uint_as_float(rp[(lane + 32) ^ sw]);
            float v2 = __uint_as_float(rp[(lane + 64) ^ sw]);
            float v3 = __uint_as_float(rp[(lane + 96) ^ sw]);
            float s = v0 + v1 + v2 + v3;
            #pragma unroll
            for (int off = 16; off > 0; off >>= 1) s += __shfl_xor_sync(0xffffffffu, s, off);
            float mu = s * (1.0f / 128.0f);
            float d0 = v0 - mu, d1 = v1 - mu, d2 = v2 - mu, d3 = v3 - mu;
            float q = d0 * d0 + d1 * d1 + d2 * d2 + d3 * d3;
            #pragma unroll
            for (int off = 16; off > 0; off >>= 1) q += __shfl_xor_sync(0xffffffffu, q, off);
            float rstd = rsqrtf(q * (1.0f / 128.0f) + 1e-5f);
            rp[lane ^ sw]        = f2tf(d0 * rstd * w0 + b0);
            rp[(lane + 32) ^ sw] = f2tf(d1 * rstd * w1 + b1);
            rp[(lane + 64) ^ sw] = f2tf(d2 * rstd * w2 + b2);
            rp[(lane + 96) ^ sw] = f2tf(d3 * rstd * w3 + b3);
        }
    }

    /* GEMM: D[j][d] = sum_h os[j][h] * W[d][h]  (M=64, N=128, K=128) */
    const int wm = wid & 1, wn = wid >> 1;
    const int g = lane >> 2, t = lane & 3;

    float c[2][4][4];
    #pragma unroll
    for (int m = 0; m < 2; m++)
        #pragma unroll
        for (int nt = 0; nt < 4; nt++)
            { c[m][nt][0] = 0; c[m][nt][1] = 0; c[m][nt][2] = 0; c[m][nt][3] = 0; }

    for (int kc = 0; kc < 128; kc += 32) {
        __syncthreads();   /* also orders LN writes before first chunk's reads */
        #pragma unroll
        for (int p = 0; p < 4; p++) {
            int s = tid + p * 256;
            int dd = s >> 3, k4 = (s & 7) << 2;
            *(uint4*)&Wk[dd * 32 + (k4 ^ ((dd & 7) << 2))] =
                *(const uint4*)(g_wO + dd * 128 + kc + k4);
        }
        __syncthreads();

        #pragma unroll
        for (int ks = 0; ks < 32; ks += 8) {
            uint32_t a[2][4], b[4][2];
            #pragma unroll
            for (int m = 0; m < 2; m++) {
                int row = wm * 32 + m * 16 + g;
                int sw = (row & 7) << 2;
                int k = kc + ks + t;
                a[m][0] = os[row * 128 + (k ^ sw)];
                a[m][1] = os[(row + 8) * 128 + (k ^ sw)];
                a[m][2] = os[row * 128 + ((k + 4) ^ sw)];
                a[m][3] = os[(row + 8) * 128 + ((k + 4) ^ sw)];
            }
            #pragma unroll
            for (int nt = 0; nt < 4; nt++) {
                int dd = wn * 32 + nt * 8 + g;
                int sw = (dd & 7) << 2;
                b[nt][0] = Wk[dd * 32 + ((ks + t) ^ sw)];
                b[nt][1] = Wk[dd * 32 + ((ks + t + 4) ^ sw)];
            }
            #pragma unroll
            for (int m = 0; m < 2; m++)
                #pragma unroll
                for (int nt = 0; nt < 4; nt++)
                    mma_tf32(c[m][nt], a[m], b[nt]);
        }
    }

    /* epilogue: gate multiply + store */
    #pragma unroll
    for (int m = 0; m < 2; m++) {
        #pragma unroll
        for (int nt = 0; nt < 4; nt++) {
            int jrow = j0 + wm * 32 + m * 16 + g;
            int dcol = wn * 32 + nt * 8 + 2 * t;
            size_t base = ((size_t)i * 512 + jrow) * 128 + dcol;
            const float* cc = c[m][nt];
            float2 gt0 = *(const float2*)(g_gate + base);
            float2 gt1 = *(const float2*)(g_gate + base + 8 * 128);
            float2 v0 = make_float2(cc[0] * gt0.x, cc[1] * gt0.y);
            float2 v1 = make_float2(cc[2] * gt1.x, cc[3] * gt1.y);
            *(float2*)(outp + base)            = v0;
            *(float2*)(outp + base + 8 * 128)  = v1;
        }
    }
}

/* ------------------------------- launch ---------------------------------- */
extern "C" void kernel_launch(void* const* d_in, const int* in_sizes, int n_in,
                              void* d_out, int out_size)
{
    const float* pair     = (const float*)d_in[0];
    const float* ln_in_w  = (const float*)d_in[1];
    const float* ln_in_b  = (const float*)d_in[2];
    const float* p_in_w   = (const float*)d_in[3];
    const float* g_in_w   = (const float*)d_in[4];
    const float* ln_out_w = (const float*)d_in[5];
    const float* ln_out_b = (const float*)d_in[6];
    const float* p_out_w  = (const float*)d_in[7];
    const float* g_out_w  = (const float*)d_in[8];
    float* out = (float*)d_out;

    kprep<<<(640 * 128 + 128 * 128 + 255) / 256, 256>>>(p_in_w, g_in_w, g_out_w, p_out_w);
    kln<<<NPAIR / 8, 256>>>(pair, ln_in_w, ln_in_b);
    kproj2<<<dim3(5, 2048), 256>>>();
    kgemm<<<dim3(4, 4, 128), 256>>>();
    kout<<<dim3(8, 512), 256>>>(ln_out_w, ln_out_b, out);
}

// round 13
// speedup vs baseline: 3.5342x; 1.2231x over previous
#include <cuda_runtime.h>
#include <cstdint>
#include <cstddef>

#define NROW 512
#define DDIM 128
#define NPAIR (NROW * NROW)          /* 262144 rows */

/* -------- scratch (static device globals; no allocations allowed) -------- */
static __device__ float    g_left [(size_t)DDIM * NPAIR];   /* tf32 bits, [d][i*512+k] */
static __device__ float    g_right[(size_t)DDIM * NPAIR];   /* tf32 bits, [d][j*512+k] */
static __device__ float    g_gate [(size_t)NPAIR * DDIM];   /* fp32, [row][e] */
static __device__ float    g_outT [(size_t)DDIM * NPAIR];   /* fp32, [d][i*512+j] */
static __device__ uint32_t g_wC   [640 * DDIM];             /* proj weights tf32 [n][k] */
static __device__ uint32_t g_wO   [DDIM * DDIM];            /* p_out_w tf32 [d][h] */

/* ------------------------------ helpers ---------------------------------- */
__device__ __forceinline__ uint32_t f2tf(float x) {
    uint32_t r;
    asm("cvt.rna.tf32.f32 %0, %1;" : "=r"(r) : "f"(x));
    return r;
}

__device__ __forceinline__ void mma_tf32(float* c, const uint32_t* a, const uint32_t* b) {
    asm volatile("mma.sync.aligned.m16n8k8.row.col.f32.tf32.tf32.f32 "
                 "{%0,%1,%2,%3}, {%4,%5,%6,%7}, {%8,%9}, {%0,%1,%2,%3};"
                 : "+f"(c[0]), "+f"(c[1]), "+f"(c[2]), "+f"(c[3])
                 : "r"(a[0]), "r"(a[1]), "r"(a[2]), "r"(a[3]),
                   "r"(b[0]), "r"(b[1]));
}

__device__ __forceinline__ float sigf(float x) {
    return 1.0f / (1.0f + __expf(-x));
}

#define CP_ASYNC16(dst_u32, src_ptr) \
    asm volatile("cp.async.cg.shared.global [%0], [%1], 16;" :: "r"(dst_u32), "l"(src_ptr) : "memory")
#define CP_COMMIT() asm volatile("cp.async.commit_group;" ::: "memory")
#define CP_WAIT0()  asm volatile("cp.async.wait_group 0;" ::: "memory")
#define CP_WAIT1()  asm volatile("cp.async.wait_group 1;" ::: "memory")

/* ------------------------- weight prep ----------------------------------- */
/* g_wC tile t<4: n 0..63 = p_in cols t*64..t*64+63, n 64..127 = matching    */
/* g_in cols. t==4: g_out. tf32 [n][k].                                      */
__global__ void kprep(const float* __restrict__ p_in_w, const float* __restrict__ g_in_w,
                      const float* __restrict__ g_out_w, const float* __restrict__ p_out_w)
{
    int idx = blockIdx.x * blockDim.x + threadIdx.x;
    if (idx < 640 * 128) {
        int r = idx >> 7, k = idx & 127;
        int t = r >> 7, u = r & 127;
        float v;
        if (t < 4) v = (u < 64) ? p_in_w[(t * 64 + u) * 128 + k]
                                : g_in_w[(t * 64 + u - 64) * 128 + k];
        else       v = g_out_w[u * 128 + k];
        g_wC[idx] = f2tf(v);
    } else if (idx < 640 * 128 + 128 * 128) {
        int k2 = idx - 640 * 128;
        g_wO[k2] = f2tf(p_out_w[k2]);   /* [d][h] */
    }
}

/* --------- stage 1: fused LN + 5-tile projection, 48 KB static smem ------ */
/* X: 64 rows x 128 k (swizzled);  Wc: 128 n x 32 k chunk (swizzled).        */
/* Warp n-frags pair p (f<2) with matching g (f>=2) so sigmoid fusion is     */
/* register-only — no smem staging, no epilogue syncs.                       */
__global__ void __launch_bounds__(256) kprojF(const float* __restrict__ pair,
                                              const float* __restrict__ lnw,
                                              const float* __restrict__ lnb)
{
    __shared__ uint32_t X [64 * 128];   /* 32 KB */
    __shared__ uint32_t Wc[128 * 32];   /* 16 KB */

    const size_t rowbase = (size_t)blockIdx.x * 64;
    const int tid = threadIdx.x;
    const int wid = tid >> 5, lane = tid & 31;
    const int wm = wid & 1, wn = wid >> 1;
    const int g = lane >> 2, t4 = lane & 3;

    const unsigned wsm = (unsigned)__cvta_generic_to_shared(Wc);

    /* ---- LayerNorm 64 rows -> tf32 X (swizzled) ---- */
    {
        float4 w4 = *(const float4*)(lnw + lane * 4);
        float4 b4 = *(const float4*)(lnb + lane * 4);
        for (int r = wid; r < 64; r += 8) {
            float4 x = *(const float4*)(pair + (rowbase + r) * 128 + lane * 4);
            float s = x.x + x.y + x.z + x.w;
            #pragma unroll
            for (int o = 16; o > 0; o >>= 1) s += __shfl_xor_sync(0xffffffffu, s, o);
            float mu = s * (1.0f / 128.0f);
            float d0 = x.x - mu, d1 = x.y - mu, d2 = x.z - mu, d3 = x.w - mu;
            float q = d0 * d0 + d1 * d1 + d2 * d2 + d3 * d3;
            #pragma unroll
            for (int o = 16; o > 0; o >>= 1) q += __shfl_xor_sync(0xffffffffu, q, o);
            float rstd = rsqrtf(q * (1.0f / 128.0f) + 1e-5f);
            uint4 o4;
            o4.x = f2tf(d0 * rstd * w4.x + b4.x);
            o4.y = f2tf(d1 * rstd * w4.y + b4.y);
            o4.z = f2tf(d2 * rstd * w4.z + b4.z);
            o4.w = f2tf(d3 * rstd * w4.w + b4.w);
            *(uint4*)&X[r * 128 + ((lane * 4) ^ ((r & 7) << 2))] = o4;
        }
    }

    /* n-frag column bases: f<2 -> p half, f>=2 -> g half (or gate spans)    */
    int ncol[4];
    ncol[0] = wn * 16;      ncol[1] = wn * 16 + 8;
    ncol[2] = 64 + ncol[0]; ncol[3] = 64 + ncol[1];

    /* ---- 5 n-tiles ---- */
    for (int t = 0; t < 5; t++) {
        float c[2][4][4];
        #pragma unroll
        for (int m = 0; m < 2; m++)
            #pragma unroll
            for (int f = 0; f < 4; f++)
                { c[m][f][0] = 0; c[m][f][1] = 0; c[m][f][2] = 0; c[m][f][3] = 0; }

        for (int kc = 0; kc < 128; kc += 32) {
            __syncthreads();   /* Wc free; (t==0,kc==0) also orders X writes */
            /* load W chunk: 128 n-rows x 32 k, swizzled */
            #pragma unroll
            for (int p = 0; p < 4; p++) {
                int s = tid + p * 256;
                int r = s >> 3, k4 = (s & 7) << 2;
                int phys = k4 ^ ((r & 7) << 2);
                CP_ASYNC16(wsm + (unsigned)(r * 32 + phys) * 4u,
                           g_wC + (size_t)(t * 128 + r) * 128 + kc + k4);
            }
            CP_COMMIT();
            CP_WAIT0();
            __syncthreads();

            #pragma unroll
            for (int ks = 0; ks < 32; ks += 8) {
                uint32_t a[2][4], b[4][2];
                #pragma unroll
                for (int m = 0; m < 2; m++) {
                    int row = wm * 32 + m * 16 + g;
                    int sw0 = (row & 7) << 2;
                    int k = kc + ks + t4;
                    a[m][0] = X[row * 128 + (k ^ sw0)];
                    a[m][1] = X[(row + 8) * 128 + (k ^ sw0)];
                    a[m][2] = X[row * 128 + ((k + 4) ^ sw0)];
                    a[m][3] = X[(row + 8) * 128 + ((k + 4) ^ sw0)];
                }
                #pragma unroll
                for (int f = 0; f < 4; f++) {
                    int nr = ncol[f] + g;
                    int sw = (nr & 7) << 2;
                    b[f][0] = Wc[nr * 32 + ((ks + t4) ^ sw)];
                    b[f][1] = Wc[nr * 32 + ((ks + t4 + 4) ^ sw)];
                }
                #pragma unroll
                for (int m = 0; m < 2; m++)
                    #pragma unroll
                    for (int f = 0; f < 4; f++)
                        mma_tf32(c[m][f], a[m], b[f]);
            }
        }

        /* ---- register-only epilogue ---- */
        if (t < 4) {
            /* pair product: left/right, channel-major, tf32-at-rest */
            #pragma unroll
            for (int m = 0; m < 2; m++) {
                int row = (int)rowbase + wm * 32 + m * 16 + g;
                #pragma unroll
                for (int f = 0; f < 2; f++) {
                    int h  = ncol[f] + 2 * t4;      /* 0..62 even */
                    int hg = t * 64 + h;
                    float* dst = (hg < 128) ? g_left : g_right;
                    size_t pl = (size_t)(hg & 127) * NPAIR;
                    const float* cp = c[m][f];
                    const float* cg = c[m][f + 2];
                    dst[pl + row]             = __uint_as_float(f2tf(sigf(cg[0]) * cp[0]));
                    dst[pl + NPAIR + row]     = __uint_as_float(f2tf(sigf(cg[1]) * cp[1]));
                    dst[pl + row + 8]         = __uint_as_float(f2tf(sigf(cg[2]) * cp[2]));
                    dst[pl + NPAIR + row + 8] = __uint_as_float(f2tf(sigf(cg[3]) * cp[3]));
                }
            }
        } else {
            /* gate tile: sigmoid, row-major fp32 */
            #pragma unroll
            for (int m = 0; m < 2; m++) {
                size_t row = rowbase + wm * 32 + m * 16 + g;
                #pragma unroll
                for (int f = 0; f < 4; f++) {
                    int h = ncol[f] + 2 * t4;
                    const float* cc = c[m][f];
                    float2 v0 = make_float2(sigf(cc[0]), sigf(cc[1]));
                    float2 v1 = make_float2(sigf(cc[2]), sigf(cc[3]));
                    *(float2*)(g_gate + row * 128 + h)       = v0;
                    *(float2*)(g_gate + (row + 8) * 128 + h) = v1;
                }
            }
        }
    }
}

/* --------- stage 2: 128 batched GEMM-NT 512x512x512, cp.async 3-stage ---- */
__device__ __forceinline__ int sw_addr(int row, int k) {
    return row * 16 + (k ^ (((row >> 1) & 3) << 2));
}

__global__ void __launch_bounds__(256) kgemm()
{
    __shared__ uint32_t As[3 * 2048];
    __shared__ uint32_t Bs[3 * 2048];

    const int d = blockIdx.z;
    const float* Ag = g_left  + (size_t)d * NPAIR + (size_t)blockIdx.y * 128 * 512;
    const float* Bg = g_right + (size_t)d * NPAIR + (size_t)blockIdx.x * 128 * 512;

    const int tid  = threadIdx.x;
    const int wid  = tid >> 5, lane = tid & 31;
    const int wm   = wid & 1;
    const int wn   = wid >> 1;
    const int g    = lane >> 2;
    const int t    = lane & 3;

    const int lr0 = tid >> 2;
    const int lc4 = (tid & 3) << 2;
    const int pk  = lc4 ^ (((lr0 >> 1) & 3) << 2);

    const unsigned aBase = (unsigned)__cvta_generic_to_shared(As);
    const unsigned bBase = (unsigned)__cvta_generic_to_shared(Bs);
    const unsigned off0 = (unsigned)(lr0 * 16 + pk) * 4u;
    const unsigned off1 = (unsigned)((lr0 + 64) * 16 + pk) * 4u;

    float c[16][4];
    #pragma unroll
    for (int q = 0; q < 16; q++) { c[q][0] = 0; c[q][1] = 0; c[q][2] = 0; c[q][3] = 0; }

    #pragma unroll
    for (int pc = 0; pc < 2; pc++) {
        const float* as = Ag + (size_t)lr0 * 512 + pc * 16 + lc4;
        const float* bs = Bg + (size_t)lr0 * 512 + pc * 16 + lc4;
        unsigned so = (unsigned)pc * 8192u;
        CP_ASYNC16(aBase + so + off0, as);
        CP_ASYNC16(aBase + so + off1, as + 64 * 512);
        CP_ASYNC16(bBase + so + off0, bs);
        CP_ASYNC16(bBase + so + off1, bs + 64 * 512);
        CP_COMMIT();
    }

    for (int cch = 0; cch < 32; cch++) {
        CP_WAIT1();
        __syncthreads();

        if (cch < 30) {
            int nc = cch + 2;
            const float* as = Ag + (size_t)lr0 * 512 + nc * 16 + lc4;
            const float* bs = Bg + (size_t)lr0 * 512 + nc * 16 + lc4;
            unsigned so = (unsigned)(nc % 3) * 8192u;
            CP_ASYNC16(aBase + so + off0, as);
            CP_ASYNC16(aBase + so + off1, as + 64 * 512);
            CP_ASYNC16(bBase + so + off0, bs);
            CP_ASYNC16(bBase + so + off1, bs + 64 * 512);
        }
        CP_COMMIT();

        const uint32_t* Asc = As + (cch % 3) * 2048;
        const uint32_t* Bsc = Bs + (cch % 3) * 2048;
        #pragma unroll
        for (int ks = 0; ks < 16; ks += 8) {
            uint32_t a[4][4], b[4][2];
            #pragma unroll
            for (int m = 0; m < 4; m++) {
                int row = wm * 64 + m * 16 + g;
                a[m][0] = Asc[sw_addr(row,     ks + t)];
                a[m][1] = Asc[sw_addr(row + 8, ks + t)];
                a[m][2] = Asc[sw_addr(row,     ks + t + 4)];
                a[m][3] = Asc[sw_addr(row + 8, ks + t + 4)];
            }
            #pragma unroll
            for (int nt = 0; nt < 4; nt++) {
                int row = wn * 32 + nt * 8 + g;
                b[nt][0] = Bsc[sw_addr(row, ks + t)];
                b[nt][1] = Bsc[sw_addr(row, ks + t + 4)];
            }
            #pragma unroll
            for (int m = 0; m < 4; m++)
                #pragma unroll
                for (int nt = 0; nt < 4; nt++)
                    mma_tf32(c[m * 4 + nt], a[m], b[nt]);
        }
    }

    const float inv = 1.0f / 512.0f;
    float* C = g_outT + (size_t)d * NPAIR;
    const int rbase = blockIdx.y * 128 + wm * 64;
    const int cbase = blockIdx.x * 128 + wn * 32;
    #pragma unroll
    for (int m = 0; m < 4; m++) {
        #pragma unroll
        for (int nt = 0; nt < 4; nt++) {
            const float* cc = c[m * 4 + nt];
            int row = rbase + m * 16 + g;
            int col = cbase + nt * 8 + 2 * t;
            float2 v0 = make_float2(cc[0] * inv, cc[1] * inv);
            float2 v1 = make_float2(cc[2] * inv, cc[3] * inv);
            *(float2*)(C + (size_t)row * 512 + col)       = v0;
            *(float2*)(C + (size_t)(row + 8) * 512 + col) = v1;
        }
    }
}

/* --------- stage 3: LN over d + p_out projection (tf32 mma) + gate ------- */
__global__ void __launch_bounds__(256) kout(const float* __restrict__ lnw,
                                            const float* __restrict__ lnb,
                                            float* __restrict__ outp)
{
    __shared__ uint32_t os[64 * 128];
    __shared__ uint32_t Wk[128 * 32];

    const int i = blockIdx.y;
    const int j0 = blockIdx.x * 64;
    const int tid = threadIdx.x;
    const int wid = tid >> 5, lane = tid & 31;

    for (int idx = tid; idx < 64 * 128; idx += 256) {
        int dd = idx >> 6, j = idx & 63;
        os[j * 128 + (dd ^ ((j & 7) << 2))] =
            __float_as_uint(g_outT[(size_t)dd * NPAIR + (size_t)i * 512 + j0 + j]);
    }
    __syncthreads();

    {
        float w0 = lnw[lane], w1 = lnw[lane + 32], w2 = lnw[lane + 64], w3 = lnw[lane + 96];
        float b0 = lnb[lane], b1 = lnb[lane + 32], b2 = lnb[lane + 64], b3 = lnb[lane + 96];
        for (int j = wid; j < 64; j += 8) {
            int sw = (j & 7) << 2;
            uint32_t* rp = os + j * 128;
            float v0 = __uint_as_float(rp[lane ^ sw]);
            float v1 = __uint_as_float(rp[(lane + 32) ^ sw]);
            float v2 = __uint_as_float(rp[(lane + 64) ^ sw]);
            float v3 = __uint_as_float(rp[(lane + 96) ^ sw]);
            float s = v0 + v1 + v2 + v3;
            #pragma unroll
            for (int off = 16; off > 0; off >>= 1) s += __shfl_xor_sync(0xffffffffu, s, off);
            float mu = s * (1.0f / 128.0f);
            float d0 = v0 - mu, d1 = v1 - mu, d2 = v2 - mu, d3 = v3 - mu;
            float q = d0 * d0 + d1 * d1 + d2 * d2 + d3 * d3;
            #pragma unroll
            for (int off = 16; off > 0; off >>= 1) q += __shfl_xor_sync(0xffffffffu, q, off);
            float rstd = rsqrtf(q * (1.0f / 128.0f) + 1e-5f);
            rp[lane ^ sw]        = f2tf(d0 * rstd * w0 + b0);
            rp[(lane + 32) ^ sw] = f2tf(d1 * rstd * w1 + b1);
            rp[(lane + 64) ^ sw] = f2tf(d2 * rstd * w2 + b2);
            rp[(lane + 96) ^ sw] = f2tf(d3 * rstd * w3 + b3);
        }
    }

    const int wm = wid & 1, wn = wid >> 1;
    const int g = lane >> 2, t = lane & 3;

    float c[2][4][4];
    #pragma unroll
    for (int m = 0; m < 2; m++)
        #pragma unroll
        for (int nt = 0; nt < 4; nt++)
            { c[m][nt][0] = 0; c[m][nt][1] = 0; c[m][nt][2] = 0; c[m][nt][3] = 0; }

    for (int kc = 0; kc < 128; kc += 32) {
        __syncthreads();
        #pragma unroll
        for (int p = 0; p < 4; p++) {
            int s = tid + p * 256;
            int dd = s >> 3, k4 = (s & 7) << 2;
            *(uint4*)&Wk[dd * 32 + (k4 ^ ((dd & 7) << 2))] =
                *(const uint4*)(g_wO + dd * 128 + kc + k4);
        }
        __syncthreads();

        #pragma unroll
        for (int ks = 0; ks < 32; ks += 8) {
            uint32_t a[2][4], b[4][2];
            #pragma unroll
            for (int m = 0; m < 2; m++) {
                int row = wm * 32 + m * 16 + g;
                int sw = (row & 7) << 2;
                int k = kc + ks + t;
                a[m][0] = os[row * 128 + (k ^ sw)];
                a[m][1] = os[(row + 8) * 128 + (k ^ sw)];
                a[m][2] = os[row * 128 + ((k + 4) ^ sw)];
                a[m][3] = os[(row + 8) * 128 + ((k + 4) ^ sw)];
            }
            #pragma unroll
            for (int nt = 0; nt < 4; nt++) {
                int dd = wn * 32 + nt * 8 + g;
                int sw = (dd & 7) << 2;
                b[nt][0] = Wk[dd * 32 + ((ks + t) ^ sw)];
                b[nt][1] = Wk[dd * 32 + ((ks + t + 4) ^ sw)];
            }
            #pragma unroll
            for (int m = 0; m < 2; m++)
                #pragma unroll
                for (int nt = 0; nt < 4; nt++)
                    mma_tf32(c[m][nt], a[m], b[nt]);
        }
    }

    #pragma unroll
    for (int m = 0; m < 2; m++) {
        #pragma unroll
        for (int nt = 0; nt < 4; nt++) {
            int jrow = j0 + wm * 32 + m * 16 + g;
            int dcol = wn * 32 + nt * 8 + 2 * t;
            size_t base = ((size_t)i * 512 + jrow) * 128 + dcol;
            const float* cc = c[m][nt];
            float2 gt0 = *(const float2*)(g_gate + base);
            float2 gt1 = *(const float2*)(g_gate + base + 8 * 128);
            float2 v0 = make_float2(cc[0] * gt0.x, cc[1] * gt0.y);
            float2 v1 = make_float2(cc[2] * gt1.x, cc[3] * gt1.y);
            *(float2*)(outp + base)            = v0;
            *(float2*)(outp + base + 8 * 128)  = v1;
        }
    }
}

/* ------------------------------- launch ---------------------------------- */
extern "C" void kernel_launch(void* const* d_in, const int* in_sizes, int n_in,
                              void* d_out, int out_size)
{
    const float* pair     = (const float*)d_in[0];
    const float* ln_in_w  = (const float*)d_in[1];
    const float* ln_in_b  = (const float*)d_in[2];
    const float* p_in_w   = (const float*)d_in[3];
    const float* g_in_w   = (const float*)d_in[4];
    const float* ln_out_w = (const float*)d_in[5];
    const float* ln_out_b = (const float*)d_in[6];
    const float* p_out_w  = (const float*)d_in[7];
    const float* g_out_w  = (const float*)d_in[8];
    float* out = (float*)d_out;

    kprep<<<(640 * 128 + 128 * 128 + 255) / 256, 256>>>(p_in_w, g_in_w, g_out_w, p_out_w);
    kprojF<<<NPAIR / 64, 256>>>(pair, ln_in_w, ln_in_b);
    kgemm<<<dim3(4, 4, 128), 256>>>();
    kout<<<dim3(8, 512), 256>>>(ln_out_w, ln_out_b, out);
}

// round 14
// speedup vs baseline: 3.7809x; 1.0698x over previous
#include <cuda_runtime.h>
#include <cstdint>
#include <cstddef>

#define NROW 512
#define DDIM 128
#define NPAIR (NROW * NROW)          /* 262144 rows */

/* -------- scratch (static device globals; no allocations allowed) -------- */
static __device__ float    g_left [(size_t)DDIM * NPAIR];   /* tf32 bits, [d][i*512+k] */
static __device__ float    g_right[(size_t)DDIM * NPAIR];   /* tf32 bits, [d][j*512+k] */
static __device__ float    g_gate [(size_t)NPAIR * DDIM];   /* fp32, [row][e] */
static __device__ float    g_outT [(size_t)DDIM * NPAIR];   /* fp32, [d][i*512+j] */
static __device__ uint32_t g_wC   [640 * DDIM];             /* proj weights tf32 [n][k] */
static __device__ uint32_t g_wO   [DDIM * DDIM];            /* p_out_w tf32 [d][h] */

/* ------------------------------ helpers ---------------------------------- */
__device__ __forceinline__ uint32_t f2tf(float x) {
    uint32_t r;
    asm("cvt.rna.tf32.f32 %0, %1;" : "=r"(r) : "f"(x));
    return r;
}

__device__ __forceinline__ void mma_tf32(float* c, const uint32_t* a, const uint32_t* b) {
    asm volatile("mma.sync.aligned.m16n8k8.row.col.f32.tf32.tf32.f32 "
                 "{%0,%1,%2,%3}, {%4,%5,%6,%7}, {%8,%9}, {%0,%1,%2,%3};"
                 : "+f"(c[0]), "+f"(c[1]), "+f"(c[2]), "+f"(c[3])
                 : "r"(a[0]), "r"(a[1]), "r"(a[2]), "r"(a[3]),
                   "r"(b[0]), "r"(b[1]));
}

__device__ __forceinline__ float sigf(float x) {
    return 1.0f / (1.0f + __expf(-x));
}

#define CP_ASYNC16(dst_u32, src_ptr) \
    asm volatile("cp.async.cg.shared.global [%0], [%1], 16;" :: "r"(dst_u32), "l"(src_ptr) : "memory")
#define CP_COMMIT() asm volatile("cp.async.commit_group;" ::: "memory")
#define CP_WAIT0()  asm volatile("cp.async.wait_group 0;" ::: "memory")
#define CP_WAIT1()  asm volatile("cp.async.wait_group 1;" ::: "memory")

/* 16-word-row swizzle (same family as kgemm): conflict-free for quad frags  */
__device__ __forceinline__ int sw16(int row, int k) {
    return row * 16 + (k ^ (((row >> 1) & 3) << 2));
}

/* ------------------------- weight prep ----------------------------------- */
/* g_wC tile t<4: n 0..63 = p_in cols t*64..t*64+63, n 64..127 = matching    */
/* g_in cols. t==4: g_out. tf32 [n][k].                                      */
__global__ void kprep(const float* __restrict__ p_in_w, const float* __restrict__ g_in_w,
                      const float* __restrict__ g_out_w, const float* __restrict__ p_out_w)
{
    int idx = blockIdx.x * blockDim.x + threadIdx.x;
    if (idx < 640 * 128) {
        int r = idx >> 7, k = idx & 127;
        int t = r >> 7, u = r & 127;
        float v;
        if (t < 4) v = (u < 64) ? p_in_w[(t * 64 + u) * 128 + k]
                                : g_in_w[(t * 64 + u - 64) * 128 + k];
        else       v = g_out_w[u * 128 + k];
        g_wC[idx] = f2tf(v);
    } else if (idx < 640 * 128 + 128 * 128) {
        int k2 = idx - 640 * 128;
        g_wO[k2] = f2tf(p_out_w[k2]);   /* [d][h] */
    }
}

/* --------- stage 1: fused LN + 5-tile projection, pipelined W loads ------ */
/* X: 64 rows x 128 k (swizzled, 32 KB); Wc: 2 x (128 n x 16 k) (16 KB).     */
/* 40 W-chunks (5 tiles x 8), double-buffered cp.async: load(ci+1) overlaps  */
/* mma(ci). Epilogue is register-only (p/g paired in-warp).                  */
__global__ void __launch_bounds__(256) kprojF(const float* __restrict__ pair,
                                              const float* __restrict__ lnw,
                                              const float* __restrict__ lnb)
{
    __shared__ uint32_t X [64 * 128];     /* 32 KB */
    __shared__ uint32_t Wc[2 * 128 * 16]; /* 16 KB */

    const size_t rowbase = (size_t)blockIdx.x * 64;
    const int tid = threadIdx.x;
    const int wid = tid >> 5, lane = tid & 31;
    const int wm = wid & 1, wn = wid >> 1;
    const int g = lane >> 2, t4 = lane & 3;

    const unsigned wsm = (unsigned)__cvta_generic_to_shared(Wc);

    /* per-thread W-load mapping: 2 x 16B per chunk */
    const int lr  = tid >> 2;                    /* +64 for p=1 */
    const int lk4 = (tid & 3) << 2;

    auto issueW = [&](int cj) {
        int tt = cj >> 3, kc = (cj & 7) << 4;
        unsigned dst = wsm + (unsigned)(cj & 1) * 8192u;
        #pragma unroll
        for (int p = 0; p < 2; p++) {
            int r = lr + p * 64;
            int phys = lk4 ^ (((r >> 1) & 3) << 2);
            CP_ASYNC16(dst + (unsigned)(r * 16 + phys) * 4u,
                       g_wC + (size_t)(tt * 128 + r) * 128 + kc + lk4);
        }
    };

    /* preload chunk 0 (overlaps LN) */
    issueW(0);
    CP_COMMIT();

    /* ---- LayerNorm 64 rows -> tf32 X (swizzled) ---- */
    {
        float4 w4 = *(const float4*)(lnw + lane * 4);
        float4 b4 = *(const float4*)(lnb + lane * 4);
        for (int r = wid; r < 64; r += 8) {
            float4 x = *(const float4*)(pair + (rowbase + r) * 128 + lane * 4);
            float s = x.x + x.y + x.z + x.w;
            #pragma unroll
            for (int o = 16; o > 0; o >>= 1) s += __shfl_xor_sync(0xffffffffu, s, o);
            float mu = s * (1.0f / 128.0f);
            float d0 = x.x - mu, d1 = x.y - mu, d2 = x.z - mu, d3 = x.w - mu;
            float q = d0 * d0 + d1 * d1 + d2 * d2 + d3 * d3;
            #pragma unroll
            for (int o = 16; o > 0; o >>= 1) q += __shfl_xor_sync(0xffffffffu, q, o);
            float rstd = rsqrtf(q * (1.0f / 128.0f) + 1e-5f);
            uint4 o4;
            o4.x = f2tf(d0 * rstd * w4.x + b4.x);
            o4.y = f2tf(d1 * rstd * w4.y + b4.y);
            o4.z = f2tf(d2 * rstd * w4.z + b4.z);
            o4.w = f2tf(d3 * rstd * w4.w + b4.w);
            *(uint4*)&X[r * 128 + ((lane * 4) ^ ((r & 7) << 2))] = o4;
        }
    }

    /* n-frag column bases: f<2 -> p half, f>=2 -> matching g half           */
    int ncol[4];
    ncol[0] = wn * 16;      ncol[1] = wn * 16 + 8;
    ncol[2] = 64 + ncol[0]; ncol[3] = 64 + ncol[1];

    /* ---- 5 n-tiles, 8 pipelined 16-k chunks each ---- */
    for (int t = 0; t < 5; t++) {
        float c[2][4][4];
        #pragma unroll
        for (int m = 0; m < 2; m++)
            #pragma unroll
            for (int f = 0; f < 4; f++)
                { c[m][f][0] = 0; c[m][f][1] = 0; c[m][f][2] = 0; c[m][f][3] = 0; }

        for (int kcI = 0; kcI < 8; kcI++) {
            const int ci = t * 8 + kcI;
            __syncthreads();            /* buf[(ci+1)&1] free (mma ci-1 done); ci==0: X ready */
            if (ci < 39) issueW(ci + 1);
            CP_COMMIT();
            CP_WAIT1();                 /* load(ci) complete */
            __syncthreads();

            const uint32_t* Wb = Wc + (ci & 1) * 2048;
            const int kc = kcI << 4;

            #pragma unroll
            for (int ks = 0; ks < 16; ks += 8) {
                uint32_t a[2][4], b[4][2];
                #pragma unroll
                for (int m = 0; m < 2; m++) {
                    int row = wm * 32 + m * 16 + g;
                    int sw0 = (row & 7) << 2;
                    int k = kc + ks + t4;
                    a[m][0] = X[row * 128 + (k ^ sw0)];
                    a[m][1] = X[(row + 8) * 128 + (k ^ sw0)];
                    a[m][2] = X[row * 128 + ((k + 4) ^ sw0)];
                    a[m][3] = X[(row + 8) * 128 + ((k + 4) ^ sw0)];
                }
                #pragma unroll
                for (int f = 0; f < 4; f++) {
                    int nr = ncol[f] + g;
                    b[f][0] = Wb[sw16(nr, ks + t4)];
                    b[f][1] = Wb[sw16(nr, ks + t4 + 4)];
                }
                #pragma unroll
                for (int m = 0; m < 2; m++)
                    #pragma unroll
                    for (int f = 0; f < 4; f++)
                        mma_tf32(c[m][f], a[m], b[f]);
            }
        }

        /* ---- register-only epilogue (no smem, no syncs) ---- */
        if (t < 4) {
            #pragma unroll
            for (int m = 0; m < 2; m++) {
                int row = (int)rowbase + wm * 32 + m * 16 + g;
                #pragma unroll
                for (int f = 0; f < 2; f++) {
                    int h  = ncol[f] + 2 * t4;
                    int hg = t * 64 + h;
                    float* dst = (hg < 128) ? g_left : g_right;
                    size_t pl = (size_t)(hg & 127) * NPAIR;
                    const float* cp = c[m][f];
                    const float* cg = c[m][f + 2];
                    dst[pl + row]             = __uint_as_float(f2tf(sigf(cg[0]) * cp[0]));
                    dst[pl + NPAIR + row]     = __uint_as_float(f2tf(sigf(cg[1]) * cp[1]));
                    dst[pl + row + 8]         = __uint_as_float(f2tf(sigf(cg[2]) * cp[2]));
                    dst[pl + NPAIR + row + 8] = __uint_as_float(f2tf(sigf(cg[3]) * cp[3]));
                }
            }
        } else {
            #pragma unroll
            for (int m = 0; m < 2; m++) {
                size_t row = rowbase + wm * 32 + m * 16 + g;
                #pragma unroll
                for (int f = 0; f < 4; f++) {
                    int h = ncol[f] + 2 * t4;
                    const float* cc = c[m][f];
                    float2 v0 = make_float2(sigf(cc[0]), sigf(cc[1]));
                    float2 v1 = make_float2(sigf(cc[2]), sigf(cc[3]));
                    *(float2*)(g_gate + row * 128 + h)       = v0;
                    *(float2*)(g_gate + (row + 8) * 128 + h) = v1;
                }
            }
        }
    }
}

/* --------- stage 2: 128 batched GEMM-NT 512x512x512, cp.async 3-stage ---- */
__device__ __forceinline__ int sw_addr(int row, int k) {
    return row * 16 + (k ^ (((row >> 1) & 3) << 2));
}

__global__ void __launch_bounds__(256, 2) kgemm()
{
    __shared__ uint32_t As[3 * 2048];
    __shared__ uint32_t Bs[3 * 2048];

    const int d = blockIdx.z;
    const float* Ag = g_left  + (size_t)d * NPAIR + (size_t)blockIdx.y * 128 * 512;
    const float* Bg = g_right + (size_t)d * NPAIR + (size_t)blockIdx.x * 128 * 512;

    const int tid  = threadIdx.x;
    const int wid  = tid >> 5, lane = tid & 31;
    const int wm   = wid & 1;
    const int wn   = wid >> 1;
    const int g    = lane >> 2;
    const int t    = lane & 3;

    const int lr0 = tid >> 2;
    const int lc4 = (tid & 3) << 2;
    const int pk  = lc4 ^ (((lr0 >> 1) & 3) << 2);

    const unsigned aBase = (unsigned)__cvta_generic_to_shared(As);
    const unsigned bBase = (unsigned)__cvta_generic_to_shared(Bs);
    const unsigned off0 = (unsigned)(lr0 * 16 + pk) * 4u;
    const unsigned off1 = (unsigned)((lr0 + 64) * 16 + pk) * 4u;

    float c[16][4];
    #pragma unroll
    for (int q = 0; q < 16; q++) { c[q][0] = 0; c[q][1] = 0; c[q][2] = 0; c[q][3] = 0; }

    #pragma unroll
    for (int pc = 0; pc < 2; pc++) {
        const float* as = Ag + (size_t)lr0 * 512 + pc * 16 + lc4;
        const float* bs = Bg + (size_t)lr0 * 512 + pc * 16 + lc4;
        unsigned so = (unsigned)pc * 8192u;
        CP_ASYNC16(aBase + so + off0, as);
        CP_ASYNC16(aBase + so + off1, as + 64 * 512);
        CP_ASYNC16(bBase + so + off0, bs);
        CP_ASYNC16(bBase + so + off1, bs + 64 * 512);
        CP_COMMIT();
    }

    for (int cch = 0; cch < 32; cch++) {
        CP_WAIT1();
        __syncthreads();

        if (cch < 30) {
            int nc = cch + 2;
            const float* as = Ag + (size_t)lr0 * 512 + nc * 16 + lc4;
            const float* bs = Bg + (size_t)lr0 * 512 + nc * 16 + lc4;
            unsigned so = (unsigned)(nc % 3) * 8192u;
            CP_ASYNC16(aBase + so + off0, as);
            CP_ASYNC16(aBase + so + off1, as + 64 * 512);
            CP_ASYNC16(bBase + so + off0, bs);
            CP_ASYNC16(bBase + so + off1, bs + 64 * 512);
        }
        CP_COMMIT();

        const uint32_t* Asc = As + (cch % 3) * 2048;
        const uint32_t* Bsc = Bs + (cch % 3) * 2048;
        #pragma unroll
        for (int ks = 0; ks < 16; ks += 8) {
            uint32_t a[4][4], b[4][2];
            #pragma unroll
            for (int m = 0; m < 4; m++) {
                int row = wm * 64 + m * 16 + g;
                a[m][0] = Asc[sw_addr(row,     ks + t)];
                a[m][1] = Asc[sw_addr(row + 8, ks + t)];
                a[m][2] = Asc[sw_addr(row,     ks + t + 4)];
                a[m][3] = Asc[sw_addr(row + 8, ks + t + 4)];
            }
            #pragma unroll
            for (int nt = 0; nt < 4; nt++) {
                int row = wn * 32 + nt * 8 + g;
                b[nt][0] = Bsc[sw_addr(row, ks + t)];
                b[nt][1] = Bsc[sw_addr(row, ks + t + 4)];
            }
            #pragma unroll
            for (int m = 0; m < 4; m++)
                #pragma unroll
                for (int nt = 0; nt < 4; nt++)
                    mma_tf32(c[m * 4 + nt], a[m], b[nt]);
        }
    }

    const float inv = 1.0f / 512.0f;
    float* C = g_outT + (size_t)d * NPAIR;
    const int rbase = blockIdx.y * 128 + wm * 64;
    const int cbase = blockIdx.x * 128 + wn * 32;
    #pragma unroll
    for (int m = 0; m < 4; m++) {
        #pragma unroll
        for (int nt = 0; nt < 4; nt++) {
            const float* cc = c[m * 4 + nt];
            int row = rbase + m * 16 + g;
            int col = cbase + nt * 8 + 2 * t;
            float2 v0 = make_float2(cc[0] * inv, cc[1] * inv);
            float2 v1 = make_float2(cc[2] * inv, cc[3] * inv);
            *(float2*)(C + (size_t)row * 512 + col)       = v0;
            *(float2*)(C + (size_t)(row + 8) * 512 + col) = v1;
        }
    }
}

/* --------- stage 3: LN over d + p_out projection (tf32 mma) + gate ------- */
__global__ void __launch_bounds__(256) kout(const float* __restrict__ lnw,
                                            const float* __restrict__ lnb,
                                            float* __restrict__ outp)
{
    __shared__ uint32_t os[64 * 128];
    __shared__ uint32_t Wk[128 * 32];

    const int i = blockIdx.y;
    const int j0 = blockIdx.x * 64;
    const int tid = threadIdx.x;
    const int wid = tid >> 5, lane = tid & 31;

    for (int idx = tid; idx < 64 * 128; idx += 256) {
        int dd = idx >> 6, j = idx & 63;
        os[j * 128 + (dd ^ ((j & 7) << 2))] =
            __float_as_uint(g_outT[(size_t)dd * NPAIR + (size_t)i * 512 + j0 + j]);
    }
    __syncthreads();

    {
        float w0 = lnw[lane], w1 = lnw[lane + 32], w2 = lnw[lane + 64], w3 = lnw[lane + 96];
        float b0 = lnb[lane], b1 = lnb[lane + 32], b2 = lnb[lane + 64], b3 = lnb[lane + 96];
        for (int j = wid; j < 64; j += 8) {
            int sw = (j & 7) << 2;
            uint32_t* rp = os + j * 128;
            float v0 = __uint_as_float(rp[lane ^ sw]);
            float v1 = __uint_as_float(rp[(lane + 32) ^ sw]);
            float v2 = __uint_as_float(rp[(lane + 64) ^ sw]);
            float v3 = __uint_as_float(rp[(lane + 96) ^ sw]);
            float s = v0 + v1 + v2 + v3;
            #pragma unroll
            for (int off = 16; off > 0; off >>= 1) s += __shfl_xor_sync(0xffffffffu, s, off);
            float mu = s * (1.0f / 128.0f);
            float d0 = v0 - mu, d1 = v1 - mu, d2 = v2 - mu, d3 = v3 - mu;
            float q = d0 * d0 + d1 * d1 + d2 * d2 + d3 * d3;
            #pragma unroll
            for (int off = 16; off > 0; off >>= 1) q += __shfl_xor_sync(0xffffffffu, q, off);
            float rstd = rsqrtf(q * (1.0f / 128.0f) + 1e-5f);
            rp[lane ^ sw]        = f2tf(d0 * rstd * w0 + b0);
            rp[(lane + 32) ^ sw] = f2tf(d1 * rstd * w1 + b1);
            rp[(lane + 64) ^ sw] = f2tf(d2 * rstd * w2 + b2);
            rp[(lane + 96) ^ sw] = f2tf(d3 * rstd * w3 + b3);
        }
    }

    const int wm = wid & 1, wn = wid >> 1;
    const int g = lane >> 2, t = lane & 3;

    float c[2][4][4];
    #pragma unroll
    for (int m = 0; m < 2; m++)
        #pragma unroll
        for (int nt = 0; nt < 4; nt++)
            { c[m][nt][0] = 0; c[m][nt][1] = 0; c[m][nt][2] = 0; c[m][nt][3] = 0; }

    for (int kc = 0; kc < 128; kc += 32) {
        __syncthreads();
        #pragma unroll
        for (int p = 0; p < 4; p++) {
            int s = tid + p * 256;
            int dd = s >> 3, k4 = (s & 7) << 2;
            *(uint4*)&Wk[dd * 32 + (k4 ^ ((dd & 7) << 2))] =
                *(const uint4*)(g_wO + dd * 128 + kc + k4);
        }
        __syncthreads();

        #pragma unroll
        for (int ks = 0; ks < 32; ks += 8) {
            uint32_t a[2][4], b[4][2];
            #pragma unroll
            for (int m = 0; m < 2; m++) {
                int row = wm * 32 + m * 16 + g;
                int sw = (row & 7) << 2;
                int k = kc + ks + t;
                a[m][0] = os[row * 128 + (k ^ sw)];
                a[m][1] = os[(row + 8) * 128 + (k ^ sw)];
                a[m][2] = os[row * 128 + ((k + 4) ^ sw)];
                a[m][3] = os[(row + 8) * 128 + ((k + 4) ^ sw)];
            }
            #pragma unroll
            for (int nt = 0; nt < 4; nt++) {
                int dd = wn * 32 + nt * 8 + g;
                int sw = (dd & 7) << 2;
                b[nt][0] = Wk[dd * 32 + ((ks + t) ^ sw)];
                b[nt][1] = Wk[dd * 32 + ((ks + t + 4) ^ sw)];
            }
            #pragma unroll
            for (int m = 0; m < 2; m++)
                #pragma unroll
                for (int nt = 0; nt < 4; nt++)
                    mma_tf32(c[m][nt], a[m], b[nt]);
        }
    }

    #pragma unroll
    for (int m = 0; m < 2; m++) {
        #pragma unroll
        for (int nt = 0; nt < 4; nt++) {
            int jrow = j0 + wm * 32 + m * 16 + g;
            int dcol = wn * 32 + nt * 8 + 2 * t;
            size_t base = ((size_t)i * 512 + jrow) * 128 + dcol;
            const float* cc = c[m][nt];
            float2 gt0 = *(const float2*)(g_gate + base);
            float2 gt1 = *(const float2*)(g_gate + base + 8 * 128);
            float2 v0 = make_float2(cc[0] * gt0.x, cc[1] * gt0.y);
            float2 v1 = make_float2(cc[2] * gt1.x, cc[3] * gt1.y);
            *(float2*)(outp + base)            = v0;
            *(float2*)(outp + base + 8 * 128)  = v1;
        }
    }
}

/* ------------------------------- launch ---------------------------------- */
extern "C" void kernel_launch(void* const* d_in, const int* in_sizes, int n_in,
                              void* d_out, int out_size)
{
    const float* pair     = (const float*)d_in[0];
    const float* ln_in_w  = (const float*)d_in[1];
    const float* ln_in_b  = (const float*)d_in[2];
    const float* p_in_w   = (const float*)d_in[3];
    const float* g_in_w   = (const float*)d_in[4];
    const float* ln_out_w = (const float*)d_in[5];
    const float* ln_out_b = (const float*)d_in[6];
    const float* p_out_w  = (const float*)d_in[7];
    const float* g_out_w  = (const float*)d_in[8];
    float* out = (float*)d_out;

    kprep<<<(640 * 128 + 128 * 128 + 255) / 256, 256>>>(p_in_w, g_in_w, g_out_w, p_out_w);
    kprojF<<<NPAIR / 64, 256>>>(pair, ln_in_w, ln_in_b);
    kgemm<<<dim3(4, 4, 128), 256>>>();
    kout<<<dim3(8, 512), 256>>>(ln_out_w, ln_out_b, out);
}

// round 15
// speedup vs baseline: 4.0372x; 1.0678x over previous
#include <cuda_runtime.h>
#include <cstdint>
#include <cstddef>

#define NROW 512
#define DDIM 128
#define NPAIR (NROW * NROW)          /* 262144 rows */

/* -------- scratch (static device globals; no allocations allowed) -------- */
static __device__ float    g_left [(size_t)DDIM * NPAIR];   /* tf32 bits, [d][i*512+k] */
static __device__ float    g_right[(size_t)DDIM * NPAIR];   /* tf32 bits, [d][j*512+k] */
static __device__ float    g_gate [(size_t)NPAIR * DDIM];   /* fp32, [row][e] */
static __device__ float    g_outT [(size_t)DDIM * NPAIR];   /* fp32, [d][i*512+j] */
static __device__ uint32_t g_wC   [640 * DDIM];             /* proj weights tf32 [n][k] */
static __device__ uint32_t g_wO   [DDIM * DDIM];            /* p_out_w tf32 [d][h] */

/* ------------------------------ helpers ---------------------------------- */
__device__ __forceinline__ uint32_t f2tf(float x) {
    uint32_t r;
    asm("cvt.rna.tf32.f32 %0, %1;" : "=r"(r) : "f"(x));
    return r;
}

__device__ __forceinline__ void mma_tf32(float* c, const uint32_t* a, const uint32_t* b) {
    asm volatile("mma.sync.aligned.m16n8k8.row.col.f32.tf32.tf32.f32 "
                 "{%0,%1,%2,%3}, {%4,%5,%6,%7}, {%8,%9}, {%0,%1,%2,%3};"
                 : "+f"(c[0]), "+f"(c[1]), "+f"(c[2]), "+f"(c[3])
                 : "r"(a[0]), "r"(a[1]), "r"(a[2]), "r"(a[3]),
                   "r"(b[0]), "r"(b[1]));
}

__device__ __forceinline__ float sigf(float x) {
    return 1.0f / (1.0f + __expf(-x));
}

#define CP_ASYNC16(dst_u32, src_ptr) \
    asm volatile("cp.async.cg.shared.global [%0], [%1], 16;" :: "r"(dst_u32), "l"(src_ptr) : "memory")
#define CP_COMMIT() asm volatile("cp.async.commit_group;" ::: "memory")
#define CP_WAIT1()  asm volatile("cp.async.wait_group 1;" ::: "memory")

/* 16-word-row swizzle: conflict-free for quad frags                         */
__device__ __forceinline__ int sw16(int row, int k) {
    return row * 16 + (k ^ (((row >> 1) & 3) << 2));
}

/* ------------------------- weight prep ----------------------------------- */
__global__ void kprep(const float* __restrict__ p_in_w, const float* __restrict__ g_in_w,
                      const float* __restrict__ g_out_w, const float* __restrict__ p_out_w)
{
    int idx = blockIdx.x * blockDim.x + threadIdx.x;
    if (idx < 640 * 128) {
        int r = idx >> 7, k = idx & 127;
        int t = r >> 7, u = r & 127;
        float v;
        if (t < 4) v = (u < 64) ? p_in_w[(t * 64 + u) * 128 + k]
                                : g_in_w[(t * 64 + u - 64) * 128 + k];
        else       v = g_out_w[u * 128 + k];
        g_wC[idx] = f2tf(v);
    } else if (idx < 640 * 128 + 128 * 128) {
        int k2 = idx - 640 * 128;
        g_wO[k2] = f2tf(p_out_w[k2]);   /* [d][h] */
    }
}

/* --------- stage 1: fused LN + 5-tile projection, pipelined W loads ------ */
__global__ void __launch_bounds__(256) kprojF(const float* __restrict__ pair,
                                              const float* __restrict__ lnw,
                                              const float* __restrict__ lnb)
{
    __shared__ uint32_t X [64 * 128];     /* 32 KB */
    __shared__ uint32_t Wc[2 * 128 * 16]; /* 16 KB */

    const size_t rowbase = (size_t)blockIdx.x * 64;
    const int tid = threadIdx.x;
    const int wid = tid >> 5, lane = tid & 31;
    const int wm = wid & 1, wn = wid >> 1;
    const int g = lane >> 2, t4 = lane & 3;

    const unsigned wsm = (unsigned)__cvta_generic_to_shared(Wc);

    const int lr  = tid >> 2;
    const int lk4 = (tid & 3) << 2;

    auto issueW = [&](int cj) {
        int tt = cj >> 3, kc = (cj & 7) << 4;
        unsigned dst = wsm + (unsigned)(cj & 1) * 8192u;
        #pragma unroll
        for (int p = 0; p < 2; p++) {
            int r = lr + p * 64;
            int phys = lk4 ^ (((r >> 1) & 3) << 2);
            CP_ASYNC16(dst + (unsigned)(r * 16 + phys) * 4u,
                       g_wC + (size_t)(tt * 128 + r) * 128 + kc + lk4);
        }
    };

    issueW(0);
    CP_COMMIT();

    /* ---- LayerNorm 64 rows -> tf32 X (swizzled) ---- */
    {
        float4 w4 = *(const float4*)(lnw + lane * 4);
        float4 b4 = *(const float4*)(lnb + lane * 4);
        for (int r = wid; r < 64; r += 8) {
            float4 x = *(const float4*)(pair + (rowbase + r) * 128 + lane * 4);
            float s = x.x + x.y + x.z + x.w;
            #pragma unroll
            for (int o = 16; o > 0; o >>= 1) s += __shfl_xor_sync(0xffffffffu, s, o);
            float mu = s * (1.0f / 128.0f);
            float d0 = x.x - mu, d1 = x.y - mu, d2 = x.z - mu, d3 = x.w - mu;
            float q = d0 * d0 + d1 * d1 + d2 * d2 + d3 * d3;
            #pragma unroll
            for (int o = 16; o > 0; o >>= 1) q += __shfl_xor_sync(0xffffffffu, q, o);
            float rstd = rsqrtf(q * (1.0f / 128.0f) + 1e-5f);
            uint4 o4;
            o4.x = f2tf(d0 * rstd * w4.x + b4.x);
            o4.y = f2tf(d1 * rstd * w4.y + b4.y);
            o4.z = f2tf(d2 * rstd * w4.z + b4.z);
            o4.w = f2tf(d3 * rstd * w4.w + b4.w);
            *(uint4*)&X[r * 128 + ((lane * 4) ^ ((r & 7) << 2))] = o4;
        }
    }

    int ncol[4];
    ncol[0] = wn * 16;      ncol[1] = wn * 16 + 8;
    ncol[2] = 64 + ncol[0]; ncol[3] = 64 + ncol[1];

    for (int t = 0; t < 5; t++) {
        float c[2][4][4];
        #pragma unroll
        for (int m = 0; m < 2; m++)
            #pragma unroll
            for (int f = 0; f < 4; f++)
                { c[m][f][0] = 0; c[m][f][1] = 0; c[m][f][2] = 0; c[m][f][3] = 0; }

        for (int kcI = 0; kcI < 8; kcI++) {
            const int ci = t * 8 + kcI;
            __syncthreads();
            if (ci < 39) issueW(ci + 1);
            CP_COMMIT();
            CP_WAIT1();
            __syncthreads();

            const uint32_t* Wb = Wc + (ci & 1) * 2048;
            const int kc = kcI << 4;

            #pragma unroll
            for (int ks = 0; ks < 16; ks += 8) {
                uint32_t a[2][4], b[4][2];
                #pragma unroll
                for (int m = 0; m < 2; m++) {
                    int row = wm * 32 + m * 16 + g;
                    int sw0 = (row & 7) << 2;
                    int k = kc + ks + t4;
                    a[m][0] = X[row * 128 + (k ^ sw0)];
                    a[m][1] = X[(row + 8) * 128 + (k ^ sw0)];
                    a[m][2] = X[row * 128 + ((k + 4) ^ sw0)];
                    a[m][3] = X[(row + 8) * 128 + ((k + 4) ^ sw0)];
                }
                #pragma unroll
                for (int f = 0; f < 4; f++) {
                    int nr = ncol[f] + g;
                    b[f][0] = Wb[sw16(nr, ks + t4)];
                    b[f][1] = Wb[sw16(nr, ks + t4 + 4)];
                }
                #pragma unroll
                for (int m = 0; m < 2; m++)
                    #pragma unroll
                    for (int f = 0; f < 4; f++)
                        mma_tf32(c[m][f], a[m], b[f]);
            }
        }

        if (t < 4) {
            #pragma unroll
            for (int m = 0; m < 2; m++) {
                int row = (int)rowbase + wm * 32 + m * 16 + g;
                #pragma unroll
                for (int f = 0; f < 2; f++) {
                    int h  = ncol[f] + 2 * t4;
                    int hg = t * 64 + h;
                    float* dst = (hg < 128) ? g_left : g_right;
                    size_t pl = (size_t)(hg & 127) * NPAIR;
                    const float* cp = c[m][f];
                    const float* cg = c[m][f + 2];
                    dst[pl + row]             = __uint_as_float(f2tf(sigf(cg[0]) * cp[0]));
                    dst[pl + NPAIR + row]     = __uint_as_float(f2tf(sigf(cg[1]) * cp[1]));
                    dst[pl + row + 8]         = __uint_as_float(f2tf(sigf(cg[2]) * cp[2]));
                    dst[pl + NPAIR + row + 8] = __uint_as_float(f2tf(sigf(cg[3]) * cp[3]));
                }
            }
        } else {
            #pragma unroll
            for (int m = 0; m < 2; m++) {
                size_t row = rowbase + wm * 32 + m * 16 + g;
                #pragma unroll
                for (int f = 0; f < 4; f++) {
                    int h = ncol[f] + 2 * t4;
                    const float* cc = c[m][f];
                    float2 v0 = make_float2(sigf(cc[0]), sigf(cc[1]));
                    float2 v1 = make_float2(sigf(cc[2]), sigf(cc[3]));
                    *(float2*)(g_gate + row * 128 + h)       = v0;
                    *(float2*)(g_gate + (row + 8) * 128 + h) = v1;
                }
            }
        }
    }
}

/* --------- stage 2: batched GEMM-NT, k=32 chunks, 3-stage, 96 KB dyn ----- */
/* stage = 128 rows x 32 k words (16 KB per matrix); swizzle (row&7)<<2.     */
__global__ void __launch_bounds__(256, 2) kgemm()
{
    extern __shared__ uint32_t dsm[];
    uint32_t* As = dsm;              /* 3 x 4096 words */
    uint32_t* Bs = dsm + 3 * 4096;

    const int d = blockIdx.z;
    const float* Ag = g_left  + (size_t)d * NPAIR + (size_t)blockIdx.y * 128 * 512;
    const float* Bg = g_right + (size_t)d * NPAIR + (size_t)blockIdx.x * 128 * 512;

    const int tid  = threadIdx.x;
    const int wid  = tid >> 5, lane = tid & 31;
    const int wm   = wid & 1;
    const int wn   = wid >> 1;
    const int g    = lane >> 2;
    const int t    = lane & 3;

    const unsigned aBase = (unsigned)__cvta_generic_to_shared(As);
    const unsigned bBase = (unsigned)__cvta_generic_to_shared(Bs);

    auto issueAB = [&](int nc) {
        unsigned so = (unsigned)(nc % 3) * 16384u;
        #pragma unroll
        for (int q = 0; q < 4; q++) {
            int s = tid + q * 256;
            int r = s >> 3, k4 = (s & 7) << 2;
            int phys = k4 ^ ((r & 7) << 2);
            unsigned off = so + (unsigned)(r * 32 + phys) * 4u;
            CP_ASYNC16(aBase + off, Ag + (size_t)r * 512 + nc * 32 + k4);
            CP_ASYNC16(bBase + off, Bg + (size_t)r * 512 + nc * 32 + k4);
        }
    };

    float c[16][4];
    #pragma unroll
    for (int q = 0; q < 16; q++) { c[q][0] = 0; c[q][1] = 0; c[q][2] = 0; c[q][3] = 0; }

    issueAB(0); CP_COMMIT();
    issueAB(1); CP_COMMIT();

    for (int cch = 0; cch < 16; cch++) {
        CP_WAIT1();
        __syncthreads();

        if (cch < 14) issueAB(cch + 2);
        CP_COMMIT();

        const uint32_t* Asc = As + (cch % 3) * 4096;
        const uint32_t* Bsc = Bs + (cch % 3) * 4096;
        #pragma unroll
        for (int ks = 0; ks < 32; ks += 8) {
            uint32_t a[4][4], b[4][2];
            #pragma unroll
            for (int m = 0; m < 4; m++) {
                int row = wm * 64 + m * 16 + g;
                int sw = (row & 7) << 2;
                a[m][0] = Asc[row * 32 + ((ks + t) ^ sw)];
                a[m][1] = Asc[(row + 8) * 32 + ((ks + t) ^ sw)];
                a[m][2] = Asc[row * 32 + ((ks + t + 4) ^ sw)];
                a[m][3] = Asc[(row + 8) * 32 + ((ks + t + 4) ^ sw)];
            }
            #pragma unroll
            for (int nt = 0; nt < 4; nt++) {
                int rb = wn * 32 + nt * 8 + g;
                int swb = (rb & 7) << 2;
                b[nt][0] = Bsc[rb * 32 + ((ks + t) ^ swb)];
                b[nt][1] = Bsc[rb * 32 + ((ks + t + 4) ^ swb)];
            }
            #pragma unroll
            for (int m = 0; m < 4; m++)
                #pragma unroll
                for (int nt = 0; nt < 4; nt++)
                    mma_tf32(c[m * 4 + nt], a[m], b[nt]);
        }
        __syncthreads();
    }

    const float inv = 1.0f / 512.0f;
    float* C = g_outT + (size_t)d * NPAIR;
    const int rbase = blockIdx.y * 128 + wm * 64;
    const int cbase = blockIdx.x * 128 + wn * 32;
    #pragma unroll
    for (int m = 0; m < 4; m++) {
        #pragma unroll
        for (int nt = 0; nt < 4; nt++) {
            const float* cc = c[m * 4 + nt];
            int row = rbase + m * 16 + g;
            int col = cbase + nt * 8 + 2 * t;
            float2 v0 = make_float2(cc[0] * inv, cc[1] * inv);
            float2 v1 = make_float2(cc[2] * inv, cc[3] * inv);
            *(float2*)(C + (size_t)row * 512 + col)       = v0;
            *(float2*)(C + (size_t)(row + 8) * 512 + col) = v1;
        }
    }
}

/* --------- stage 3: LN + p_out proj (tf32 mma), pipelined W, 64 KB dyn --- */
__global__ void __launch_bounds__(256) kout(const float* __restrict__ lnw,
                                            const float* __restrict__ lnb,
                                            float* __restrict__ outp)
{
    extern __shared__ uint32_t dso[];
    uint32_t* os = dso;              /* 64 x 128 words, 32 KB */
    uint32_t* Wk = dso + 8192;       /* 2 x (128 x 32) words, 32 KB */

    const int i = blockIdx.y;
    const int j0 = blockIdx.x * 64;
    const int tid = threadIdx.x;
    const int wid = tid >> 5, lane = tid & 31;

    const unsigned wBase = (unsigned)__cvta_generic_to_shared(Wk);

    auto issueWO = [&](int kc) {    /* kc = chunk index 0..3, 32 k each */
        unsigned dst = wBase + (unsigned)(kc & 1) * 16384u;
        #pragma unroll
        for (int q = 0; q < 4; q++) {
            int s = tid + q * 256;
            int dd = s >> 3, k4 = (s & 7) << 2;
            int phys = k4 ^ ((dd & 7) << 2);
            CP_ASYNC16(dst + (unsigned)(dd * 32 + phys) * 4u,
                       g_wO + dd * 128 + kc * 32 + k4);
        }
    };

    issueWO(0);
    CP_COMMIT();

    for (int idx = tid; idx < 64 * 128; idx += 256) {
        int dd = idx >> 6, j = idx & 63;
        os[j * 128 + (dd ^ ((j & 7) << 2))] =
            __float_as_uint(g_outT[(size_t)dd * NPAIR + (size_t)i * 512 + j0 + j]);
    }
    __syncthreads();

    {
        float w0 = lnw[lane], w1 = lnw[lane + 32], w2 = lnw[lane + 64], w3 = lnw[lane + 96];
        float b0 = lnb[lane], b1 = lnb[lane + 32], b2 = lnb[lane + 64], b3 = lnb[lane + 96];
        for (int j = wid; j < 64; j += 8) {
            int sw = (j & 7) << 2;
            uint32_t* rp = os + j * 128;
            float v0 = __uint_as_float(rp[lane ^ sw]);
            float v1 = __uint_as_float(rp[(lane + 32) ^ sw]);
            float v2 = __uint_as_float(rp[(lane + 64) ^ sw]);
            float v3 = __uint_as_float(rp[(lane + 96) ^ sw]);
            float s = v0 + v1 + v2 + v3;
            #pragma unroll
            for (int off = 16; off > 0; off >>= 1) s += __shfl_xor_sync(0xffffffffu, s, off);
            float mu = s * (1.0f / 128.0f);
            float d0 = v0 - mu, d1 = v1 - mu, d2 = v2 - mu, d3 = v3 - mu;
            float q = d0 * d0 + d1 * d1 + d2 * d2 + d3 * d3;
            #pragma unroll
            for (int off = 16; off > 0; off >>= 1) q += __shfl_xor_sync(0xffffffffu, q, off);
            float rstd = rsqrtf(q * (1.0f / 128.0f) + 1e-5f);
            rp[lane ^ sw]        = f2tf(d0 * rstd * w0 + b0);
            rp[(lane + 32) ^ sw] = f2tf(d1 * rstd * w1 + b1);
            rp[(lane + 64) ^ sw] = f2tf(d2 * rstd * w2 + b2);
            rp[(lane + 96) ^ sw] = f2tf(d3 * rstd * w3 + b3);
        }
    }

    const int wm = wid & 1, wn = wid >> 1;
    const int g = lane >> 2, t = lane & 3;

    float c[2][4][4];
    #pragma unroll
    for (int m = 0; m < 2; m++)
        #pragma unroll
        for (int nt = 0; nt < 4; nt++)
            { c[m][nt][0] = 0; c[m][nt][1] = 0; c[m][nt][2] = 0; c[m][nt][3] = 0; }

    for (int kcI = 0; kcI < 4; kcI++) {
        __syncthreads();             /* prev mma done with buf (kcI+1)&1; kcI==0: LN done */
        if (kcI < 3) issueWO(kcI + 1);
        CP_COMMIT();
        CP_WAIT1();
        __syncthreads();

        const uint32_t* Wb = Wk + (kcI & 1) * 4096;
        const int kc = kcI * 32;

        #pragma unroll
        for (int ks = 0; ks < 32; ks += 8) {
            uint32_t a[2][4], b[4][2];
            #pragma unroll
            for (int m = 0; m < 2; m++) {
                int row = wm * 32 + m * 16 + g;
                int sw = (row & 7) << 2;
                int k = kc + ks + t;
                a[m][0] = os[row * 128 + (k ^ sw)];
                a[m][1] = os[(row + 8) * 128 + (k ^ sw)];
                a[m][2] = os[row * 128 + ((k + 4) ^ sw)];
                a[m][3] = os[(row + 8) * 128 + ((k + 4) ^ sw)];
            }
            #pragma unroll
            for (int nt = 0; nt < 4; nt++) {
                int dd = wn * 32 + nt * 8 + g;
                int sw = (dd & 7) << 2;
                b[nt][0] = Wb[dd * 32 + ((ks + t) ^ sw)];
                b[nt][1] = Wb[dd * 32 + ((ks + t + 4) ^ sw)];
            }
            #pragma unroll
            for (int m = 0; m < 2; m++)
                #pragma unroll
                for (int nt = 0; nt < 4; nt++)
                    mma_tf32(c[m][nt], a[m], b[nt]);
        }
    }

    #pragma unroll
    for (int m = 0; m < 2; m++) {
        #pragma unroll
        for (int nt = 0; nt < 4; nt++) {
            int jrow = j0 + wm * 32 + m * 16 + g;
            int dcol = wn * 32 + nt * 8 + 2 * t;
            size_t base = ((size_t)i * 512 + jrow) * 128 + dcol;
            const float* cc = c[m][nt];
            float2 gt0 = *(const float2*)(g_gate + base);
            float2 gt1 = *(const float2*)(g_gate + base + 8 * 128);
            float2 v0 = make_float2(cc[0] * gt0.x, cc[1] * gt0.y);
            float2 v1 = make_float2(cc[2] * gt1.x, cc[3] * gt1.y);
            *(float2*)(outp + base)            = v0;
            *(float2*)(outp + base + 8 * 128)  = v1;
        }
    }
}

/* ------------------------------- launch ---------------------------------- */
extern "C" void kernel_launch(void* const* d_in, const int* in_sizes, int n_in,
                              void* d_out, int out_size)
{
    const float* pair     = (const float*)d_in[0];
    const float* ln_in_w  = (const float*)d_in[1];
    const float* ln_in_b  = (const float*)d_in[2];
    const float* p_in_w   = (const float*)d_in[3];
    const float* g_in_w   = (const float*)d_in[4];
    const float* ln_out_w = (const float*)d_in[5];
    const float* ln_out_b = (const float*)d_in[6];
    const float* p_out_w  = (const float*)d_in[7];
    const float* g_out_w  = (const float*)d_in[8];
    float* out = (float*)d_out;

    cudaFuncSetAttribute(kgemm, cudaFuncAttributeMaxDynamicSharedMemorySize, 98304);
    cudaFuncSetAttribute(kout,  cudaFuncAttributeMaxDynamicSharedMemorySize, 65536);

    kprep<<<(640 * 128 + 128 * 128 + 255) / 256, 256>>>(p_in_w, g_in_w, g_out_w, p_out_w);
    kprojF<<<NPAIR / 64, 256>>>(pair, ln_in_w, ln_in_b);
    kgemm<<<dim3(4, 4, 128), 256, 98304>>>();
    kout<<<dim3(8, 512), 256, 65536>>>(ln_out_w, ln_out_b, out);
}

// round 16
// speedup vs baseline: 4.2078x; 1.0423x over previous
#include <cuda_runtime.h>
#include <cstdint>
#include <cstddef>

#define NROW 512
#define DDIM 128
#define NPAIR (NROW * NROW)          /* 262144 rows */

/* -------- scratch (static device globals; no allocations allowed) -------- */
static __device__ float    g_left [(size_t)DDIM * NPAIR];   /* tf32 bits, [d][i*512+k] */
static __device__ float    g_right[(size_t)DDIM * NPAIR];   /* tf32 bits, [d][j*512+k] */
static __device__ float    g_gate [(size_t)NPAIR * DDIM];   /* fp32, [row][e] */
static __device__ float    g_outT [(size_t)DDIM * NPAIR];   /* fp32, [d][i*512+j] */
static __device__ uint32_t g_wC   [640 * DDIM];             /* proj weights tf32 [n][k] */
static __device__ uint32_t g_wO   [DDIM * DDIM];            /* p_out_w tf32 [d][h] */

/* ------------------------------ helpers ---------------------------------- */
__device__ __forceinline__ uint32_t f2tf(float x) {
    uint32_t r;
    asm("cvt.rna.tf32.f32 %0, %1;" : "=r"(r) : "f"(x));
    return r;
}

__device__ __forceinline__ void mma_tf32(float* c, const uint32_t* a, const uint32_t* b) {
    asm volatile("mma.sync.aligned.m16n8k8.row.col.f32.tf32.tf32.f32 "
                 "{%0,%1,%2,%3}, {%4,%5,%6,%7}, {%8,%9}, {%0,%1,%2,%3};"
                 : "+f"(c[0]), "+f"(c[1]), "+f"(c[2]), "+f"(c[3])
                 : "r"(a[0]), "r"(a[1]), "r"(a[2]), "r"(a[3]),
                   "r"(b[0]), "r"(b[1]));
}

__device__ __forceinline__ float sigf(float x) {
    return 1.0f / (1.0f + __expf(-x));
}

#define CP_ASYNC16(dst_u32, src_ptr) \
    asm volatile("cp.async.cg.shared.global [%0], [%1], 16;" :: "r"(dst_u32), "l"(src_ptr) : "memory")
#define CP_COMMIT() asm volatile("cp.async.commit_group;" ::: "memory")
#define CP_WAIT1()  asm volatile("cp.async.wait_group 1;" ::: "memory")

/* 16-word-row swizzle: conflict-free for quad frags                         */
__device__ __forceinline__ int sw16(int row, int k) {
    return row * 16 + (k ^ (((row >> 1) & 3) << 2));
}

/* ------------------------- weight prep ----------------------------------- */
__global__ void kprep(const float* __restrict__ p_in_w, const float* __restrict__ g_in_w,
                      const float* __restrict__ g_out_w, const float* __restrict__ p_out_w)
{
    int idx = blockIdx.x * blockDim.x + threadIdx.x;
    if (idx < 640 * 128) {
        int r = idx >> 7, k = idx & 127;
        int t = r >> 7, u = r & 127;
        float v;
        if (t < 4) v = (u < 64) ? p_in_w[(t * 64 + u) * 128 + k]
                                : g_in_w[(t * 64 + u - 64) * 128 + k];
        else       v = g_out_w[u * 128 + k];
        g_wC[idx] = f2tf(v);
    } else if (idx < 640 * 128 + 128 * 128) {
        int k2 = idx - 640 * 128;
        g_wO[k2] = f2tf(p_out_w[k2]);   /* [d][h] */
    }
}

/* --------- stage 1: fused LN + 5-tile projection, M=128 tile ------------- */
/* X: 128 rows x 128 k (64 KB); Wc: 2 x (128 n x 16 k) (16 KB). 80 KB dyn.   */
/* Warps 4x2: wm=wid&3 (32 rows), wn=wid>>2 (32 p-cols + matching 32 g).     */
__global__ void __launch_bounds__(256, 2) kprojF(const float* __restrict__ pair,
                                                 const float* __restrict__ lnw,
                                                 const float* __restrict__ lnb)
{
    extern __shared__ uint32_t psm[];
    uint32_t* X  = psm;               /* 128 x 128 words */
    uint32_t* Wc = psm + 16384;       /* 2 x 2048 words  */

    const size_t rowbase = (size_t)blockIdx.x * 128;
    const int tid = threadIdx.x;
    const int wid = tid >> 5, lane = tid & 31;
    const int wm = wid & 3, wn = wid >> 2;
    const int g = lane >> 2, t4 = lane & 3;

    const unsigned wsm = (unsigned)__cvta_generic_to_shared(Wc);

    const int lr  = tid >> 2;
    const int lk4 = (tid & 3) << 2;

    auto issueW = [&](int cj) {
        int tt = cj >> 3, kc = (cj & 7) << 4;
        unsigned dst = wsm + (unsigned)(cj & 1) * 8192u;
        #pragma unroll
        for (int p = 0; p < 2; p++) {
            int r = lr + p * 64;
            int phys = lk4 ^ (((r >> 1) & 3) << 2);
            CP_ASYNC16(dst + (unsigned)(r * 16 + phys) * 4u,
                       g_wC + (size_t)(tt * 128 + r) * 128 + kc + lk4);
        }
    };

    issueW(0);
    CP_COMMIT();

    /* ---- LayerNorm 128 rows -> tf32 X (swizzled) ---- */
    {
        float4 w4 = *(const float4*)(lnw + lane * 4);
        float4 b4 = *(const float4*)(lnb + lane * 4);
        for (int r = wid; r < 128; r += 8) {
            float4 x = *(const float4*)(pair + (rowbase + r) * 128 + lane * 4);
            float s = x.x + x.y + x.z + x.w;
            #pragma unroll
            for (int o = 16; o > 0; o >>= 1) s += __shfl_xor_sync(0xffffffffu, s, o);
            float mu = s * (1.0f / 128.0f);
            float d0 = x.x - mu, d1 = x.y - mu, d2 = x.z - mu, d3 = x.w - mu;
            float q = d0 * d0 + d1 * d1 + d2 * d2 + d3 * d3;
            #pragma unroll
            for (int o = 16; o > 0; o >>= 1) q += __shfl_xor_sync(0xffffffffu, q, o);
            float rstd = rsqrtf(q * (1.0f / 128.0f) + 1e-5f);
            uint4 o4;
            o4.x = f2tf(d0 * rstd * w4.x + b4.x);
            o4.y = f2tf(d1 * rstd * w4.y + b4.y);
            o4.z = f2tf(d2 * rstd * w4.z + b4.z);
            o4.w = f2tf(d3 * rstd * w4.w + b4.w);
            *(uint4*)&X[r * 128 + ((lane * 4) ^ ((r & 7) << 2))] = o4;
        }
    }

    /* n-frag column bases: f<4 -> p cols, f>=4 -> matching g cols           */
    int ncol[8];
    #pragma unroll
    for (int f = 0; f < 4; f++) {
        ncol[f]     = wn * 32 + f * 8;
        ncol[f + 4] = 64 + ncol[f];
    }

    for (int t = 0; t < 5; t++) {
        float c[2][8][4];
        #pragma unroll
        for (int m = 0; m < 2; m++)
            #pragma unroll
            for (int f = 0; f < 8; f++)
                { c[m][f][0] = 0; c[m][f][1] = 0; c[m][f][2] = 0; c[m][f][3] = 0; }

        for (int kcI = 0; kcI < 8; kcI++) {
            const int ci = t * 8 + kcI;
            __syncthreads();
            if (ci < 39) issueW(ci + 1);
            CP_COMMIT();
            CP_WAIT1();
            __syncthreads();

            const uint32_t* Wb = Wc + (ci & 1) * 2048;
            const int kc = kcI << 4;

            #pragma unroll
            for (int ks = 0; ks < 16; ks += 8) {
                uint32_t a[2][4], b[8][2];
                #pragma unroll
                for (int m = 0; m < 2; m++) {
                    int row = wm * 32 + m * 16 + g;
                    int sw0 = (row & 7) << 2;
                    int k = kc + ks + t4;
                    a[m][0] = X[row * 128 + (k ^ sw0)];
                    a[m][1] = X[(row + 8) * 128 + (k ^ sw0)];
                    a[m][2] = X[row * 128 + ((k + 4) ^ sw0)];
                    a[m][3] = X[(row + 8) * 128 + ((k + 4) ^ sw0)];
                }
                #pragma unroll
                for (int f = 0; f < 8; f++) {
                    int nr = ncol[f] + g;
                    b[f][0] = Wb[sw16(nr, ks + t4)];
                    b[f][1] = Wb[sw16(nr, ks + t4 + 4)];
                }
                #pragma unroll
                for (int m = 0; m < 2; m++)
                    #pragma unroll
                    for (int f = 0; f < 8; f++)
                        mma_tf32(c[m][f], a[m], b[f]);
            }
        }

        /* ---- register-only epilogue ---- */
        if (t < 4) {
            #pragma unroll
            for (int m = 0; m < 2; m++) {
                int row = (int)rowbase + wm * 32 + m * 16 + g;
                #pragma unroll
                for (int f = 0; f < 4; f++) {
                    int h  = ncol[f] + 2 * t4;      /* p col, 0..62 even */
                    int hg = t * 64 + h;
                    float* dst = (hg < 128) ? g_left : g_right;
                    size_t pl = (size_t)(hg & 127) * NPAIR;
                    const float* cp = c[m][f];
                    const float* cg = c[m][f + 4];
                    dst[pl + row]             = __uint_as_float(f2tf(sigf(cg[0]) * cp[0]));
                    dst[pl + NPAIR + row]     = __uint_as_float(f2tf(sigf(cg[1]) * cp[1]));
                    dst[pl + row + 8]         = __uint_as_float(f2tf(sigf(cg[2]) * cp[2]));
                    dst[pl + NPAIR + row + 8] = __uint_as_float(f2tf(sigf(cg[3]) * cp[3]));
                }
            }
        } else {
            #pragma unroll
            for (int m = 0; m < 2; m++) {
                size_t row = rowbase + wm * 32 + m * 16 + g;
                #pragma unroll
                for (int f = 0; f < 8; f++) {
                    int h = ncol[f] + 2 * t4;
                    const float* cc = c[m][f];
                    float2 v0 = make_float2(sigf(cc[0]), sigf(cc[1]));
                    float2 v1 = make_float2(sigf(cc[2]), sigf(cc[3]));
                    *(float2*)(g_gate + row * 128 + h)       = v0;
                    *(float2*)(g_gate + (row + 8) * 128 + h) = v1;
                }
            }
        }
    }
}

/* --------- stage 2: batched GEMM-NT, k=32 chunks, 3-stage, 96 KB dyn ----- */
__global__ void __launch_bounds__(256, 2) kgemm()
{
    extern __shared__ uint32_t dsm[];
    uint32_t* As = dsm;              /* 3 x 4096 words */
    uint32_t* Bs = dsm + 3 * 4096;

    const int d = blockIdx.z;
    const float* Ag = g_left  + (size_t)d * NPAIR + (size_t)blockIdx.y * 128 * 512;
    const float* Bg = g_right + (size_t)d * NPAIR + (size_t)blockIdx.x * 128 * 512;

    const int tid  = threadIdx.x;
    const int wid  = tid >> 5, lane = tid & 31;
    const int wm   = wid & 1;
    const int wn   = wid >> 1;
    const int g    = lane >> 2;
    const int t    = lane & 3;

    const unsigned aBase = (unsigned)__cvta_generic_to_shared(As);
    const unsigned bBase = (unsigned)__cvta_generic_to_shared(Bs);

    auto issueAB = [&](int nc) {
        unsigned so = (unsigned)(nc % 3) * 16384u;
        #pragma unroll
        for (int q = 0; q < 4; q++) {
            int s = tid + q * 256;
            int r = s >> 3, k4 = (s & 7) << 2;
            int phys = k4 ^ ((r & 7) << 2);
            unsigned off = so + (unsigned)(r * 32 + phys) * 4u;
            CP_ASYNC16(aBase + off, Ag + (size_t)r * 512 + nc * 32 + k4);
            CP_ASYNC16(bBase + off, Bg + (size_t)r * 512 + nc * 32 + k4);
        }
    };

    float c[16][4];
    #pragma unroll
    for (int q = 0; q < 16; q++) { c[q][0] = 0; c[q][1] = 0; c[q][2] = 0; c[q][3] = 0; }

    issueAB(0); CP_COMMIT();
    issueAB(1); CP_COMMIT();

    for (int cch = 0; cch < 16; cch++) {
        CP_WAIT1();
        __syncthreads();

        if (cch < 14) issueAB(cch + 2);
        CP_COMMIT();

        const uint32_t* Asc = As + (cch % 3) * 4096;
        const uint32_t* Bsc = Bs + (cch % 3) * 4096;
        #pragma unroll
        for (int ks = 0; ks < 32; ks += 8) {
            uint32_t a[4][4], b[4][2];
            #pragma unroll
            for (int m = 0; m < 4; m++) {
                int row = wm * 64 + m * 16 + g;
                int sw = (row & 7) << 2;
                a[m][0] = Asc[row * 32 + ((ks + t) ^ sw)];
                a[m][1] = Asc[(row + 8) * 32 + ((ks + t) ^ sw)];
                a[m][2] = Asc[row * 32 + ((ks + t + 4) ^ sw)];
                a[m][3] = Asc[(row + 8) * 32 + ((ks + t + 4) ^ sw)];
            }
            #pragma unroll
            for (int nt = 0; nt < 4; nt++) {
                int rb = wn * 32 + nt * 8 + g;
                int swb = (rb & 7) << 2;
                b[nt][0] = Bsc[rb * 32 + ((ks + t) ^ swb)];
                b[nt][1] = Bsc[rb * 32 + ((ks + t + 4) ^ swb)];
            }
            #pragma unroll
            for (int m = 0; m < 4; m++)
                #pragma unroll
                for (int nt = 0; nt < 4; nt++)
                    mma_tf32(c[m * 4 + nt], a[m], b[nt]);
        }
        __syncthreads();
    }

    const float inv = 1.0f / 512.0f;
    float* C = g_outT + (size_t)d * NPAIR;
    const int rbase = blockIdx.y * 128 + wm * 64;
    const int cbase = blockIdx.x * 128 + wn * 32;
    #pragma unroll
    for (int m = 0; m < 4; m++) {
        #pragma unroll
        for (int nt = 0; nt < 4; nt++) {
            const float* cc = c[m * 4 + nt];
            int row = rbase + m * 16 + g;
            int col = cbase + nt * 8 + 2 * t;
            float2 v0 = make_float2(cc[0] * inv, cc[1] * inv);
            float2 v1 = make_float2(cc[2] * inv, cc[3] * inv);
            *(float2*)(C + (size_t)row * 512 + col)       = v0;
            *(float2*)(C + (size_t)(row + 8) * 512 + col) = v1;
        }
    }
}

/* --------- stage 3: LN + p_out proj (tf32 mma), pipelined W, 64 KB dyn --- */
__global__ void __launch_bounds__(256) kout(const float* __restrict__ lnw,
                                            const float* __restrict__ lnb,
                                            float* __restrict__ outp)
{
    extern __shared__ uint32_t dso[];
    uint32_t* os = dso;              /* 64 x 128 words, 32 KB */
    uint32_t* Wk = dso + 8192;       /* 2 x (128 x 32) words, 32 KB */

    const int i = blockIdx.y;
    const int j0 = blockIdx.x * 64;
    const int tid = threadIdx.x;
    const int wid = tid >> 5, lane = tid & 31;

    const unsigned wBase = (unsigned)__cvta_generic_to_shared(Wk);

    auto issueWO = [&](int kc) {
        unsigned dst = wBase + (unsigned)(kc & 1) * 16384u;
        #pragma unroll
        for (int q = 0; q < 4; q++) {
            int s = tid + q * 256;
            int dd = s >> 3, k4 = (s & 7) << 2;
            int phys = k4 ^ ((dd & 7) << 2);
            CP_ASYNC16(dst + (unsigned)(dd * 32 + phys) * 4u,
                       g_wO + dd * 128 + kc * 32 + k4);
        }
    };

    issueWO(0);
    CP_COMMIT();

    for (int idx = tid; idx < 64 * 128; idx += 256) {
        int dd = idx >> 6, j = idx & 63;
        os[j * 128 + (dd ^ ((j & 7) << 2))] =
            __float_as_uint(g_outT[(size_t)dd * NPAIR + (size_t)i * 512 + j0 + j]);
    }
    __syncthreads();

    {
        float w0 = lnw[lane], w1 = lnw[lane + 32], w2 = lnw[lane + 64], w3 = lnw[lane + 96];
        float b0 = lnb[lane], b1 = lnb[lane + 32], b2 = lnb[lane + 64], b3 = lnb[lane + 96];
        for (int j = wid; j < 64; j += 8) {
            int sw = (j & 7) << 2;
            uint32_t* rp = os + j * 128;
            float v0 = __uint_as_float(rp[lane ^ sw]);
            float v1 = __uint_as_float(rp[(lane + 32) ^ sw]);
            float v2 = __uint_as_float(rp[(lane + 64) ^ sw]);
            float v3 = __uint_as_float(rp[(lane + 96) ^ sw]);
            float s = v0 + v1 + v2 + v3;
            #pragma unroll
            for (int off = 16; off > 0; off >>= 1) s += __shfl_xor_sync(0xffffffffu, s, off);
            float mu = s * (1.0f / 128.0f);
            float d0 = v0 - mu, d1 = v1 - mu, d2 = v2 - mu, d3 = v3 - mu;
            float q = d0 * d0 + d1 * d1 + d2 * d2 + d3 * d3;
            #pragma unroll
            for (int off = 16; off > 0; off >>= 1) q += __shfl_xor_sync(0xffffffffu, q, off);
            float rstd = rsqrtf(q * (1.0f / 128.0f) + 1e-5f);
            rp[lane ^ sw]        = f2tf(d0 * rstd * w0 + b0);
            rp[(lane + 32) ^ sw] = f2tf(d1 * rstd * w1 + b1);
            rp[(lane + 64) ^ sw] = f2tf(d2 * rstd * w2 + b2);
            rp[(lane + 96) ^ sw] = f2tf(d3 * rstd * w3 + b3);
        }
    }

    const int wm = wid & 1, wn = wid >> 1;
    const int g = lane >> 2, t = lane & 3;

    float c[2][4][4];
    #pragma unroll
    for (int m = 0; m < 2; m++)
        #pragma unroll
        for (int nt = 0; nt < 4; nt++)
            { c[m][nt][0] = 0; c[m][nt][1] = 0; c[m][nt][2] = 0; c[m][nt][3] = 0; }

    for (int kcI = 0; kcI < 4; kcI++) {
        __syncthreads();
        if (kcI < 3) issueWO(kcI + 1);
        CP_COMMIT();
        CP_WAIT1();
        __syncthreads();

        const uint32_t* Wb = Wk + (kcI & 1) * 4096;
        const int kc = kcI * 32;

        #pragma unroll
        for (int ks = 0; ks < 32; ks += 8) {
            uint32_t a[2][4], b[4][2];
            #pragma unroll
            for (int m = 0; m < 2; m++) {
                int row = wm * 32 + m * 16 + g;
                int sw = (row & 7) << 2;
                int k = kc + ks + t;
                a[m][0] = os[row * 128 + (k ^ sw)];
                a[m][1] = os[(row + 8) * 128 + (k ^ sw)];
                a[m][2] = os[row * 128 + ((k + 4) ^ sw)];
                a[m][3] = os[(row + 8) * 128 + ((k + 4) ^ sw)];
            }
            #pragma unroll
            for (int nt = 0; nt < 4; nt++) {
                int dd = wn * 32 + nt * 8 + g;
                int sw = (dd & 7) << 2;
                b[nt][0] = Wb[dd * 32 + ((ks + t) ^ sw)];
                b[nt][1] = Wb[dd * 32 + ((ks + t + 4) ^ sw)];
            }
            #pragma unroll
            for (int m = 0; m < 2; m++)
                #pragma unroll
                for (int nt = 0; nt < 4; nt++)
                    mma_tf32(c[m][nt], a[m], b[nt]);
        }
    }

    #pragma unroll
    for (int m = 0; m < 2; m++) {
        #pragma unroll
        for (int nt = 0; nt < 4; nt++) {
            int jrow = j0 + wm * 32 + m * 16 + g;
            int dcol = wn * 32 + nt * 8 + 2 * t;
            size_t base = ((size_t)i * 512 + jrow) * 128 + dcol;
            const float* cc = c[m][nt];
            float2 gt0 = *(const float2*)(g_gate + base);
            float2 gt1 = *(const float2*)(g_gate + base + 8 * 128);
            float2 v0 = make_float2(cc[0] * gt0.x, cc[1] * gt0.y);
            float2 v1 = make_float2(cc[2] * gt1.x, cc[3] * gt1.y);
            *(float2*)(outp + base)            = v0;
            *(float2*)(outp + base + 8 * 128)  = v1;
        }
    }
}

/* ------------------------------- launch ---------------------------------- */
extern "C" void kernel_launch(void* const* d_in, const int* in_sizes, int n_in,
                              void* d_out, int out_size)
{
    const float* pair     = (const float*)d_in[0];
    const float* ln_in_w  = (const float*)d_in[1];
    const float* ln_in_b  = (const float*)d_in[2];
    const float* p_in_w   = (const float*)d_in[3];
    const float* g_in_w   = (const float*)d_in[4];
    const float* ln_out_w = (const float*)d_in[5];
    const float* ln_out_b = (const float*)d_in[6];
    const float* p_out_w  = (const float*)d_in[7];
    const float* g_out_w  = (const float*)d_in[8];
    float* out = (float*)d_out;

    cudaFuncSetAttribute(kprojF, cudaFuncAttributeMaxDynamicSharedMemorySize, 81920);
    cudaFuncSetAttribute(kgemm,  cudaFuncAttributeMaxDynamicSharedMemorySize, 98304);
    cudaFuncSetAttribute(kout,   cudaFuncAttributeMaxDynamicSharedMemorySize, 65536);

    kprep<<<(640 * 128 + 128 * 128 + 255) / 256, 256>>>(p_in_w, g_in_w, g_out_w, p_out_w);
    kprojF<<<NPAIR / 128, 256, 81920>>>(pair, ln_in_w, ln_in_b);
    kgemm<<<dim3(4, 4, 128), 256, 98304>>>();
    kout<<<dim3(8, 512), 256, 65536>>>(ln_out_w, ln_out_b, out);
}